// round 1
// baseline (speedup 1.0000x reference)
#include <cuda_runtime.h>

#define B_   2
#define SQ_  2048
#define SK_  2048
#define D_   1024
#define H_   16
#define HD_  64
#define P_   257
#define R_   128
#define RAD_ 256

// ---------------- scratch (device globals; no allocation allowed) -----------
__device__ float g_qh[(size_t)B_ * H_ * SQ_ * HD_];     // 16 MB
__device__ float g_kh[(size_t)B_ * H_ * SK_ * HD_];     // 16 MB
__device__ float g_vh[(size_t)B_ * H_ * SK_ * HD_];     // 16 MB
__device__ float g_relT[(size_t)H_ * P_ * HD_];         // ~1 MB
__device__ float g_qrel[(size_t)B_ * H_ * SQ_ * P_];    // 64 MB
__device__ float g_o[(size_t)B_ * SQ_ * D_];            // 16 MB

// ---------------- generic NT SGEMM: C[m,n] = sum_k A[m,k]*B[n,k] ------------
// MODE 0: C row-major [M,N].  MODE 1: head-split epilogue (M=B*S, N=H*HD),
//         writes C[((b*H+h)*S + s)*HD + hd].
template <int MODE>
__global__ __launch_bounds__(256) void sgemm_nt(
    const float* __restrict__ A, const float* __restrict__ Bm,
    float* __restrict__ C, int M, int N, int K,
    long long sA, long long sB, long long sC, int bmodB)
{
    const int z = blockIdx.z;
    A  += (long long)z * sA;
    Bm += (long long)(z % bmodB) * sB;
    C  += (long long)z * sC;

    __shared__ float As[16][128];
    __shared__ float Bs[16][128];

    const int bm = blockIdx.y * 128, bn = blockIdx.x * 128;
    const int tid = threadIdx.x;
    const int tx = tid & 15, ty = tid >> 4;

    float acc[8][8];
#pragma unroll
    for (int i = 0; i < 8; i++)
#pragma unroll
        for (int j = 0; j < 8; j++) acc[i][j] = 0.f;

    for (int k0 = 0; k0 < K; k0 += 16) {
#pragma unroll
        for (int it = 0; it < 2; it++) {
            int lin = tid * 2 + it;        // 0..511
            int row = lin >> 2;            // 0..127
            int kk4 = (lin & 3) << 2;      // 0,4,8,12
            {
                int gr = bm + row;
                float4 v = make_float4(0.f, 0.f, 0.f, 0.f);
                if (gr < M) v = *(const float4*)(A + (long long)gr * K + k0 + kk4);
                As[kk4 + 0][row] = v.x; As[kk4 + 1][row] = v.y;
                As[kk4 + 2][row] = v.z; As[kk4 + 3][row] = v.w;
            }
            {
                int gc = bn + row;
                float4 v = make_float4(0.f, 0.f, 0.f, 0.f);
                if (gc < N) v = *(const float4*)(Bm + (long long)gc * K + k0 + kk4);
                Bs[kk4 + 0][row] = v.x; Bs[kk4 + 1][row] = v.y;
                Bs[kk4 + 2][row] = v.z; Bs[kk4 + 3][row] = v.w;
            }
        }
        __syncthreads();
#pragma unroll
        for (int kk = 0; kk < 16; kk++) {
            float a[8], b[8];
            *(float4*)&a[0] = *(const float4*)&As[kk][ty * 4];
            *(float4*)&a[4] = *(const float4*)&As[kk][64 + ty * 4];
            *(float4*)&b[0] = *(const float4*)&Bs[kk][tx * 4];
            *(float4*)&b[4] = *(const float4*)&Bs[kk][64 + tx * 4];
#pragma unroll
            for (int i = 0; i < 8; i++)
#pragma unroll
                for (int j = 0; j < 8; j++) acc[i][j] += a[i] * b[j];
        }
        __syncthreads();
    }

#pragma unroll
    for (int i = 0; i < 8; i++) {
        int gr = bm + ty * 4 + (i & 3) + ((i >= 4) ? 64 : 0);
        if (gr >= M) continue;
#pragma unroll
        for (int j = 0; j < 8; j++) {
            int gc = bn + tx * 4 + (j & 3) + ((j >= 4) ? 64 : 0);
            if (gc >= N) continue;
            float v = acc[i][j];
            if (MODE == 0) {
                C[(long long)gr * N + gc] = v;
            } else {
                int b = gr >> 11, s = gr & 2047;      // M = B*2048
                int h = gc >> 6,  hd = gc & 63;       // N = 16*64
                C[(((long long)b * H_ + h) * SQ_ + s) * HD_ + hd] = v;
            }
        }
    }
}

// ---------------- E transpose: relT[h][p][d] = E[p*D + d*H + h] -------------
__global__ void transpose_E(const float* __restrict__ E, float* __restrict__ relT)
{
    int idx = blockIdx.x * blockDim.x + threadIdx.x;
    if (idx >= H_ * P_ * HD_) return;
    int h = idx / (P_ * HD_);
    int rem = idx % (P_ * HD_);
    int p = rem / HD_;
    int d = rem % HD_;
    relT[idx] = E[(long long)p * D_ + d * H_ + h];
}

// ---------------- banded flash attention ------------------------------------
// grid: (SQ/64, H, B). block 256 threads (16x16, 4x4 micro-tiles).
// Output O[b][s][hd*H + h]  (matches torch permute(0,2,3,1).flatten).
__global__ __launch_bounds__(256) void attn_kernel(
    const float* __restrict__ qh, const float* __restrict__ kh,
    const float* __restrict__ vh, const float* __restrict__ qrel,
    float* __restrict__ O)
{
    extern __shared__ float sm[];
    float* Qt   = sm;             // [64][64]  Qt[d][r]
    float* Kt   = Qt + 4096;      // [64][64]  Kt[d][c]
    float* Vs   = Kt + 4096;      // [64][64]  Vs[k][c]
    float* Pt   = Vs + 4096;      // [64][64]  Pt[k][r]
    float* Ss   = Pt + 4096;      // [64][65]  padded (row-stat reads)
    float* rowm = Ss + 64 * 65;   // 64
    float* rowl = rowm + 64;      // 64
    float* rowf = rowl + 64;      // 64

    const int i0 = blockIdx.x * 64;
    const int h = blockIdx.y, b = blockIdx.z;
    const long long hb = (long long)(b * H_ + h);
    const float* qb = qh + hb * SQ_ * HD_;
    const float* kb = kh + hb * SK_ * HD_;
    const float* vb = vh + hb * SK_ * HD_;
    const float* qr = qrel + hb * SQ_ * P_;

    const int tid = threadIdx.x;
    const int tx = tid & 15, ty = tid >> 4;

    // load Q tile transposed
    for (int l = tid; l < 1024; l += 256) {
        int r = l >> 4, d4 = (l & 15) << 2;
        float4 v = *(const float4*)(qb + (long long)(i0 + r) * HD_ + d4);
        Qt[(d4 + 0) * 64 + r] = v.x; Qt[(d4 + 1) * 64 + r] = v.y;
        Qt[(d4 + 2) * 64 + r] = v.z; Qt[(d4 + 3) * 64 + r] = v.w;
    }
    if (tid < 64) { rowm[tid] = -1e30f; rowl[tid] = 0.f; }

    float oacc[4][4];
#pragma unroll
    for (int i = 0; i < 4; i++)
#pragma unroll
        for (int j = 0; j < 4; j++) oacc[i][j] = 0.f;

    int lo = i0 - RAD_;       if (lo < 0) lo = 0;
    int hi = i0 + 64 + RAD_;  if (hi > SK_) hi = SK_;
    __syncthreads();

    for (int j0 = lo; j0 < hi; j0 += 64) {
        // load K (transposed) and V (row-major) tiles
        for (int l = tid; l < 1024; l += 256) {
            int r = l >> 4, d4 = (l & 15) << 2;
            float4 kv = *(const float4*)(kb + (long long)(j0 + r) * HD_ + d4);
            Kt[(d4 + 0) * 64 + r] = kv.x; Kt[(d4 + 1) * 64 + r] = kv.y;
            Kt[(d4 + 2) * 64 + r] = kv.z; Kt[(d4 + 3) * 64 + r] = kv.w;
            float4 vv = *(const float4*)(vb + (long long)(j0 + r) * HD_ + d4);
            *(float4*)(Vs + r * 64 + d4) = vv;
        }
        __syncthreads();

        // S = Q K^T (4x4 per thread)
        float sacc[4][4];
#pragma unroll
        for (int i = 0; i < 4; i++)
#pragma unroll
            for (int j = 0; j < 4; j++) sacc[i][j] = 0.f;
#pragma unroll
        for (int d = 0; d < 64; d++) {
            float4 a  = *(const float4*)(Qt + d * 64 + ty * 4);
            float4 bb = *(const float4*)(Kt + d * 64 + tx * 4);
            float av[4] = {a.x, a.y, a.z, a.w};
            float bv[4] = {bb.x, bb.y, bb.z, bb.w};
#pragma unroll
            for (int i = 0; i < 4; i++)
#pragma unroll
                for (int j = 0; j < 4; j++) sacc[i][j] += av[i] * bv[j];
        }

        // scale + rel_shift gather + band mask -> Ss
#pragma unroll
        for (int i = 0; i < 4; i++) {
            int r = ty * 4 + i, qi = i0 + r;
#pragma unroll
            for (int j = 0; j < 4; j++) {
                int c = tx * 4 + j, kj = j0 + c;
                int delta = kj - qi;
                float s = -1e30f;
                if (delta <= RAD_ && delta >= -RAD_) {
                    int pid = delta < -R_ ? -R_ : (delta > R_ ? R_ : delta);
                    s = (sacc[i][j] + __ldg(qr + (long long)qi * P_ + pid + R_)) * 0.125f;
                }
                Ss[r * 65 + c] = s;
            }
        }
        __syncthreads();

        // online-softmax row stats (threads 0..63, one row each)
        if (tid < 64) {
            int r = tid;
            float mold = rowm[r];
            float mx = mold;
#pragma unroll 8
            for (int c = 0; c < 64; c++) mx = fmaxf(mx, Ss[r * 65 + c]);
            float f = __expf(mold - mx);
            float sum = 0.f;
#pragma unroll 4
            for (int c = 0; c < 64; c++) {
                float p = __expf(Ss[r * 65 + c] - mx);
                sum += p;
                Pt[c * 64 + r] = p;
            }
            rowf[r] = f;
            rowm[r] = mx;
            rowl[r] = rowl[r] * f + sum;
        }
        __syncthreads();

        // rescale accumulators, O += P @ V
#pragma unroll
        for (int i = 0; i < 4; i++) {
            float fr = rowf[ty * 4 + i];
#pragma unroll
            for (int j = 0; j < 4; j++) oacc[i][j] *= fr;
        }
#pragma unroll
        for (int kk = 0; kk < 64; kk++) {
            float4 a  = *(const float4*)(Pt + kk * 64 + ty * 4);
            float4 bv = *(const float4*)(Vs + kk * 64 + tx * 4);
            float av[4] = {a.x, a.y, a.z, a.w};
            float vv[4] = {bv.x, bv.y, bv.z, bv.w};
#pragma unroll
            for (int i = 0; i < 4; i++)
#pragma unroll
                for (int j = 0; j < 4; j++) oacc[i][j] += av[i] * vv[j];
        }
        __syncthreads();
    }

    // normalize + write O[b][s][hd*H + h]
#pragma unroll
    for (int i = 0; i < 4; i++) {
        int r = ty * 4 + i;
        float inv = 1.0f / rowl[r];
#pragma unroll
        for (int j = 0; j < 4; j++) {
            int c = tx * 4 + j;   // hd
            O[((long long)b * SQ_ + i0 + r) * D_ + c * H_ + h] = oacc[i][j] * inv;
        }
    }
}

// ---------------- launch -----------------------------------------------------
extern "C" void kernel_launch(void* const* d_in, const int* in_sizes, int n_in,
                              void* d_out, int out_size)
{
    const float* Q  = (const float*)d_in[0];
    const float* K  = (const float*)d_in[1];
    const float* V  = (const float*)d_in[2];
    const float* Wq = (const float*)d_in[3];
    const float* Wk = (const float*)d_in[4];
    const float* Wv = (const float*)d_in[5];
    const float* Wo = (const float*)d_in[6];
    const float* E  = (const float*)d_in[7];
    float* out = (float*)d_out;

    float *qh, *kh, *vh, *relT, *qrel, *o;
    cudaGetSymbolAddress((void**)&qh,   g_qh);
    cudaGetSymbolAddress((void**)&kh,   g_kh);
    cudaGetSymbolAddress((void**)&vh,   g_vh);
    cudaGetSymbolAddress((void**)&relT, g_relT);
    cudaGetSymbolAddress((void**)&qrel, g_qrel);
    cudaGetSymbolAddress((void**)&o,    g_o);

    dim3 blk(256);
    dim3 gproj(1024 / 128, 4096 / 128, 1);   // (8, 32, 1)

    // projections with head-split epilogue
    sgemm_nt<1><<<gproj, blk>>>(Q, Wq, qh, 4096, 1024, 1024, 0, 0, 0, 1);
    sgemm_nt<1><<<gproj, blk>>>(K, Wk, kh, 4096, 1024, 1024, 0, 0, 0, 1);
    sgemm_nt<1><<<gproj, blk>>>(V, Wv, vh, 4096, 1024, 1024, 0, 0, 0, 1);

    // rel embedding transpose
    int nE = H_ * P_ * HD_;
    transpose_E<<<(nE + 255) / 256, 256>>>(E, relT);

    // Q_rel: per (b,h): [2048x257] = q[2048x64] @ relT[h][257x64]^T
    dim3 gqr((P_ + 127) / 128, SQ_ / 128, B_ * H_);
    sgemm_nt<0><<<gqr, blk>>>(qh, relT, qrel, SQ_, P_, HD_,
                              (long long)SQ_ * HD_, (long long)P_ * HD_,
                              (long long)SQ_ * P_, H_);

    // banded attention
    int smem = (4 * 4096 + 64 * 65 + 3 * 64) * (int)sizeof(float);   // ~83 KB
    cudaFuncSetAttribute(attn_kernel, cudaFuncAttributeMaxDynamicSharedMemorySize, smem);
    dim3 gattn(SQ_ / 64, H_, B_);
    attn_kernel<<<gattn, blk, smem>>>(qh, kh, vh, qrel, o);

    // output projection -> d_out
    sgemm_nt<0><<<gproj, blk>>>(o, Wo, out, 4096, 1024, 1024, 0, 0, 0, 1);

    (void)in_sizes; (void)n_in; (void)out_size;
}

// round 2
// speedup vs baseline: 1.6798x; 1.6798x over previous
#include <cuda_runtime.h>
#include <cstdint>

#define B_   2
#define SQ_  2048
#define SK_  2048
#define D_   1024
#define H_   16
#define HD_  64
#define P_   257
#define R_   128
#define RAD_ 256

#define BKP 36   // padded K stride for tf32 gemm smem tiles

// ---------------- scratch (device globals; no allocation allowed) -----------
__device__ float g_qh[(size_t)B_ * H_ * SQ_ * HD_];     // 16 MB
__device__ float g_kh[(size_t)B_ * H_ * SK_ * HD_];     // 16 MB
__device__ float g_vh[(size_t)B_ * H_ * SK_ * HD_];     // 16 MB
__device__ float g_relT[(size_t)H_ * P_ * HD_];         // ~1 MB
__device__ float g_qrel[(size_t)B_ * H_ * SQ_ * P_];    // 64 MB
__device__ float g_o[(size_t)B_ * SQ_ * D_];            // 16 MB

// ---------------- helpers ----------------------------------------------------
__device__ __forceinline__ uint32_t f2tf32(float x) {
    uint32_t r;
    asm("cvt.rna.tf32.f32 %0, %1;" : "=r"(r) : "f"(x));
    return r;
}

__device__ __forceinline__ void mma_tf32(float* c, const uint32_t* a, const uint32_t* b) {
    asm volatile(
        "mma.sync.aligned.m16n8k8.row.col.f32.tf32.tf32.f32 "
        "{%0,%1,%2,%3}, {%4,%5,%6,%7}, {%8,%9}, {%0,%1,%2,%3};"
        : "+f"(c[0]), "+f"(c[1]), "+f"(c[2]), "+f"(c[3])
        : "r"(a[0]), "r"(a[1]), "r"(a[2]), "r"(a[3]), "r"(b[0]), "r"(b[1]));
}

__device__ __forceinline__ void cp16(float* dst_s, const float* src_g, int sz) {
    uint32_t dst = (uint32_t)__cvta_generic_to_shared(dst_s);
    asm volatile("cp.async.cg.shared.global [%0], [%1], 16, %2;\n"
                 :: "r"(dst), "l"(src_g), "r"(sz));
}

// ---------------- tf32 tensor-core NT GEMM ----------------------------------
// C[m,n] = sum_k A[m,k] * B[n,k].  M must be a multiple of 128.
// MODE 0: C row-major [M,N].  MODE 1: head-split epilogue (M=B*S, N=H*HD).
template <int MODE>
__global__ __launch_bounds__(256) void gemm_tf32(
    const float* __restrict__ A, const float* __restrict__ Bm,
    float* __restrict__ C, int M, int N, int K,
    long long sA, long long sB, long long sC, int bmodB)
{
    extern __shared__ float smbuf[];   // 2 stages * (As 128*36 + Bs 128*36)
    const int z = blockIdx.z;
    A  += (long long)z * sA;
    Bm += (long long)(z % bmodB) * sB;
    C  += (long long)z * sC;

    const int bm = blockIdx.y * 128, bn = blockIdx.x * 128;
    const int tid = threadIdx.x;
    const int wid = tid >> 5, lane = tid & 31;
    const int wm = (wid & 3) * 32, wn = (wid >> 2) * 64;
    const int q = lane >> 2, t = lane & 3;

    const int lrow = tid >> 3;         // 0..31
    const int lcol = (tid & 7) * 4;    // 0,4,...,28

    float acc[2][8][4];
#pragma unroll
    for (int mi = 0; mi < 2; mi++)
#pragma unroll
        for (int ni = 0; ni < 8; ni++)
#pragma unroll
            for (int e = 0; e < 4; e++) acc[mi][ni][e] = 0.f;

    const int ktiles = K >> 5;

    // ---- stage issue (cp.async) ----
#define ISSUE(KT, STAGE)                                                      \
    {                                                                         \
        float* As = smbuf + (STAGE) * (2 * 128 * BKP);                        \
        float* Bs = As + 128 * BKP;                                           \
        int k0 = (KT) * 32;                                                   \
        _Pragma("unroll")                                                     \
        for (int rep = 0; rep < 4; rep++) {                                   \
            int row = rep * 32 + lrow;                                        \
            cp16(As + row * BKP + lcol,                                       \
                 A + (long long)(bm + row) * K + k0 + lcol, 16);              \
            int gb = bn + row;                                                \
            int gbc = gb < N ? gb : (N - 1);                                  \
            cp16(Bs + row * BKP + lcol,                                       \
                 Bm + (long long)gbc * K + k0 + lcol, (gb < N) ? 16 : 0);     \
        }                                                                     \
        asm volatile("cp.async.commit_group;\n");                             \
    }

    ISSUE(0, 0);

    for (int kt = 0; kt < ktiles; kt++) {
        if (kt + 1 < ktiles) {
            ISSUE(kt + 1, (kt + 1) & 1);
            asm volatile("cp.async.wait_group 1;\n");
        } else {
            asm volatile("cp.async.wait_group 0;\n");
        }
        __syncthreads();

        const float* As = smbuf + (kt & 1) * (2 * 128 * BKP);
        const float* Bs = As + 128 * BKP;
#pragma unroll
        for (int ks = 0; ks < 4; ks++) {
            const int kb = ks * 8;
            uint32_t af[2][4];
#pragma unroll
            for (int mi = 0; mi < 2; mi++) {
                int r0 = wm + mi * 16 + q;
                af[mi][0] = f2tf32(As[r0 * BKP + kb + t]);
                af[mi][1] = f2tf32(As[(r0 + 8) * BKP + kb + t]);
                af[mi][2] = f2tf32(As[r0 * BKP + kb + 4 + t]);
                af[mi][3] = f2tf32(As[(r0 + 8) * BKP + kb + 4 + t]);
            }
            uint32_t bf[8][2];
#pragma unroll
            for (int ni = 0; ni < 8; ni++) {
                int n0 = wn + ni * 8 + q;
                bf[ni][0] = f2tf32(Bs[n0 * BKP + kb + t]);
                bf[ni][1] = f2tf32(Bs[n0 * BKP + kb + 4 + t]);
            }
#pragma unroll
            for (int mi = 0; mi < 2; mi++)
#pragma unroll
                for (int ni = 0; ni < 8; ni++)
                    mma_tf32(acc[mi][ni], af[mi], bf[ni]);
        }
        __syncthreads();
    }
#undef ISSUE

    // ---- epilogue ----
#pragma unroll
    for (int mi = 0; mi < 2; mi++)
#pragma unroll
        for (int ni = 0; ni < 8; ni++) {
            int gr0 = bm + wm + mi * 16 + q;
            int gc0 = bn + wn + ni * 8 + t * 2;
#pragma unroll
            for (int e = 0; e < 4; e++) {
                int gr = gr0 + ((e >= 2) ? 8 : 0);
                int gc = gc0 + (e & 1);
                if (gc >= N) continue;
                float v = acc[mi][ni][e];
                if (MODE == 0) {
                    C[(long long)gr * N + gc] = v;
                } else {
                    int b = gr >> 11, s = gr & 2047;
                    int h = gc >> 6, hd = gc & 63;
                    C[(((long long)b * H_ + h) * SQ_ + s) * HD_ + hd] = v;
                }
            }
        }
}

// ---------------- E transpose: relT[h][p][d] = E[p*D + d*H + h] -------------
__global__ void transpose_E(const float* __restrict__ E, float* __restrict__ relT)
{
    int idx = blockIdx.x * blockDim.x + threadIdx.x;
    if (idx >= H_ * P_ * HD_) return;
    int h = idx / (P_ * HD_);
    int rem = idx % (P_ * HD_);
    int p = rem / HD_;
    int d = rem % HD_;
    relT[idx] = E[(long long)p * D_ + d * H_ + h];
}

// ---------------- banded flash attention (fp32) -----------------------------
__global__ __launch_bounds__(256) void attn_kernel(
    const float* __restrict__ qh, const float* __restrict__ kh,
    const float* __restrict__ vh, const float* __restrict__ qrel,
    float* __restrict__ O)
{
    extern __shared__ float sm[];
    float* Qt   = sm;             // [64][64]  Qt[d][r]
    float* Kt   = Qt + 4096;      // [64][64]  Kt[d][c]
    float* Vs   = Kt + 4096;      // [64][64]  Vs[k][c]
    float* Pt   = Vs + 4096;      // [64][64]  Pt[k][r]
    float* Ss   = Pt + 4096;      // [64][65]
    float* rowm = Ss + 64 * 65;
    float* rowl = rowm + 64;
    float* rowf = rowl + 64;

    const int i0 = blockIdx.x * 64;
    const int h = blockIdx.y, b = blockIdx.z;
    const long long hb = (long long)(b * H_ + h);
    const float* qb = qh + hb * SQ_ * HD_;
    const float* kb = kh + hb * SK_ * HD_;
    const float* vb = vh + hb * SK_ * HD_;
    const float* qr = qrel + hb * SQ_ * P_;

    const int tid = threadIdx.x;
    const int tx = tid & 15, ty = tid >> 4;

    for (int l = tid; l < 1024; l += 256) {
        int r = l >> 4, d4 = (l & 15) << 2;
        float4 v = *(const float4*)(qb + (long long)(i0 + r) * HD_ + d4);
        Qt[(d4 + 0) * 64 + r] = v.x; Qt[(d4 + 1) * 64 + r] = v.y;
        Qt[(d4 + 2) * 64 + r] = v.z; Qt[(d4 + 3) * 64 + r] = v.w;
    }
    if (tid < 64) { rowm[tid] = -1e30f; rowl[tid] = 0.f; }

    float oacc[4][4];
#pragma unroll
    for (int i = 0; i < 4; i++)
#pragma unroll
        for (int j = 0; j < 4; j++) oacc[i][j] = 0.f;

    int lo = i0 - RAD_;       if (lo < 0) lo = 0;
    int hi = i0 + 64 + RAD_;  if (hi > SK_) hi = SK_;
    __syncthreads();

    for (int j0 = lo; j0 < hi; j0 += 64) {
        for (int l = tid; l < 1024; l += 256) {
            int r = l >> 4, d4 = (l & 15) << 2;
            float4 kv = *(const float4*)(kb + (long long)(j0 + r) * HD_ + d4);
            Kt[(d4 + 0) * 64 + r] = kv.x; Kt[(d4 + 1) * 64 + r] = kv.y;
            Kt[(d4 + 2) * 64 + r] = kv.z; Kt[(d4 + 3) * 64 + r] = kv.w;
            float4 vv = *(const float4*)(vb + (long long)(j0 + r) * HD_ + d4);
            *(float4*)(Vs + r * 64 + d4) = vv;
        }
        __syncthreads();

        float sacc[4][4];
#pragma unroll
        for (int i = 0; i < 4; i++)
#pragma unroll
            for (int j = 0; j < 4; j++) sacc[i][j] = 0.f;
#pragma unroll
        for (int d = 0; d < 64; d++) {
            float4 a  = *(const float4*)(Qt + d * 64 + ty * 4);
            float4 bb = *(const float4*)(Kt + d * 64 + tx * 4);
            float av[4] = {a.x, a.y, a.z, a.w};
            float bv[4] = {bb.x, bb.y, bb.z, bb.w};
#pragma unroll
            for (int i = 0; i < 4; i++)
#pragma unroll
                for (int j = 0; j < 4; j++) sacc[i][j] += av[i] * bv[j];
        }

#pragma unroll
        for (int i = 0; i < 4; i++) {
            int r = ty * 4 + i, qi = i0 + r;
#pragma unroll
            for (int j = 0; j < 4; j++) {
                int c = tx * 4 + j, kj = j0 + c;
                int delta = kj - qi;
                float s = -1e30f;
                if (delta <= RAD_ && delta >= -RAD_) {
                    int pid = delta < -R_ ? -R_ : (delta > R_ ? R_ : delta);
                    s = (sacc[i][j] + __ldg(qr + (long long)qi * P_ + pid + R_)) * 0.125f;
                }
                Ss[r * 65 + c] = s;
            }
        }
        __syncthreads();

        if (tid < 64) {
            int r = tid;
            float mold = rowm[r];
            float mx = mold;
#pragma unroll 8
            for (int c = 0; c < 64; c++) mx = fmaxf(mx, Ss[r * 65 + c]);
            float f = __expf(mold - mx);
            float sum = 0.f;
#pragma unroll 4
            for (int c = 0; c < 64; c++) {
                float p = __expf(Ss[r * 65 + c] - mx);
                sum += p;
                Pt[c * 64 + r] = p;
            }
            rowf[r] = f;
            rowm[r] = mx;
            rowl[r] = rowl[r] * f + sum;
        }
        __syncthreads();

#pragma unroll
        for (int i = 0; i < 4; i++) {
            float fr = rowf[ty * 4 + i];
#pragma unroll
            for (int j = 0; j < 4; j++) oacc[i][j] *= fr;
        }
#pragma unroll
        for (int kk = 0; kk < 64; kk++) {
            float4 a  = *(const float4*)(Pt + kk * 64 + ty * 4);
            float4 bv = *(const float4*)(Vs + kk * 64 + tx * 4);
            float av[4] = {a.x, a.y, a.z, a.w};
            float vv[4] = {bv.x, bv.y, bv.z, bv.w};
#pragma unroll
            for (int i = 0; i < 4; i++)
#pragma unroll
                for (int j = 0; j < 4; j++) oacc[i][j] += av[i] * vv[j];
        }
        __syncthreads();
    }

#pragma unroll
    for (int i = 0; i < 4; i++) {
        int r = ty * 4 + i;
        float inv = 1.0f / rowl[r];
#pragma unroll
        for (int j = 0; j < 4; j++) {
            int c = tx * 4 + j;
            O[((long long)b * SQ_ + i0 + r) * D_ + c * H_ + h] = oacc[i][j] * inv;
        }
    }
}

// ---------------- launch -----------------------------------------------------
extern "C" void kernel_launch(void* const* d_in, const int* in_sizes, int n_in,
                              void* d_out, int out_size)
{
    const float* Q  = (const float*)d_in[0];
    const float* K  = (const float*)d_in[1];
    const float* V  = (const float*)d_in[2];
    const float* Wq = (const float*)d_in[3];
    const float* Wk = (const float*)d_in[4];
    const float* Wv = (const float*)d_in[5];
    const float* Wo = (const float*)d_in[6];
    const float* E  = (const float*)d_in[7];
    float* out = (float*)d_out;

    float *qh, *kh, *vh, *relT, *qrel, *o;
    cudaGetSymbolAddress((void**)&qh,   g_qh);
    cudaGetSymbolAddress((void**)&kh,   g_kh);
    cudaGetSymbolAddress((void**)&vh,   g_vh);
    cudaGetSymbolAddress((void**)&relT, g_relT);
    cudaGetSymbolAddress((void**)&qrel, g_qrel);
    cudaGetSymbolAddress((void**)&o,    g_o);

    const int gemm_smem = 2 * 2 * 128 * BKP * (int)sizeof(float);  // 73728 B
    cudaFuncSetAttribute(gemm_tf32<0>, cudaFuncAttributeMaxDynamicSharedMemorySize, gemm_smem);
    cudaFuncSetAttribute(gemm_tf32<1>, cudaFuncAttributeMaxDynamicSharedMemorySize, gemm_smem);

    dim3 blk(256);
    dim3 gproj(1024 / 128, 4096 / 128, 1);   // (8, 32, 1)

    // projections with head-split epilogue (tf32 tensor cores)
    gemm_tf32<1><<<gproj, blk, gemm_smem>>>(Q, Wq, qh, 4096, 1024, 1024, 0, 0, 0, 1);
    gemm_tf32<1><<<gproj, blk, gemm_smem>>>(K, Wk, kh, 4096, 1024, 1024, 0, 0, 0, 1);
    gemm_tf32<1><<<gproj, blk, gemm_smem>>>(V, Wv, vh, 4096, 1024, 1024, 0, 0, 0, 1);

    // rel embedding transpose
    int nE = H_ * P_ * HD_;
    transpose_E<<<(nE + 255) / 256, 256>>>(E, relT);

    // Q_rel: per (b,h): [2048x257] = q[2048x64] @ relT[h][257x64]^T
    dim3 gqr((P_ + 127) / 128, SQ_ / 128, B_ * H_);
    gemm_tf32<0><<<gqr, blk, gemm_smem>>>(qh, relT, qrel, SQ_, P_, HD_,
                                          (long long)SQ_ * HD_, (long long)P_ * HD_,
                                          (long long)SQ_ * P_, H_);

    // banded attention (fp32)
    int smem = (4 * 4096 + 64 * 65 + 3 * 64) * (int)sizeof(float);   // ~83 KB
    cudaFuncSetAttribute(attn_kernel, cudaFuncAttributeMaxDynamicSharedMemorySize, smem);
    dim3 gattn(SQ_ / 64, H_, B_);
    attn_kernel<<<gattn, blk, smem>>>(qh, kh, vh, qrel, o);

    // output projection -> d_out (tf32 tensor cores)
    gemm_tf32<0><<<gproj, blk, gemm_smem>>>(o, Wo, out, 4096, 1024, 1024, 0, 0, 0, 1);

    (void)in_sizes; (void)n_in; (void)out_size;
}

// round 3
// speedup vs baseline: 2.4569x; 1.4626x over previous
#include <cuda_runtime.h>
#include <cstdint>

#define B_   2
#define SQ_  2048
#define SK_  2048
#define D_   1024
#define H_   16
#define HD_  64
#define P_   257
#define R_   128
#define RAD_ 256

#define BKP 36   // padded K stride for tf32 gemm smem tiles
#define AST 68   // attention smem stride (68 % 32 == 4 -> conflict-free frags)

// ---------------- scratch (device globals; no allocation allowed) -----------
__device__ float g_qh[(size_t)B_ * H_ * SQ_ * HD_];     // 16 MB
__device__ float g_kh[(size_t)B_ * H_ * SK_ * HD_];     // 16 MB
__device__ float g_vh[(size_t)B_ * H_ * SK_ * HD_];     // 16 MB
__device__ float g_relT[(size_t)H_ * P_ * HD_];         // ~1 MB
__device__ float g_qrel[(size_t)B_ * H_ * SQ_ * P_];    // 64 MB
__device__ float g_o[(size_t)B_ * SQ_ * D_];            // 16 MB

// ---------------- helpers ----------------------------------------------------
__device__ __forceinline__ uint32_t f2tf32(float x) {
    uint32_t r;
    asm("cvt.rna.tf32.f32 %0, %1;" : "=r"(r) : "f"(x));
    return r;
}

__device__ __forceinline__ void mma_tf32(float* c, const uint32_t* a, const uint32_t* b) {
    asm volatile(
        "mma.sync.aligned.m16n8k8.row.col.f32.tf32.tf32.f32 "
        "{%0,%1,%2,%3}, {%4,%5,%6,%7}, {%8,%9}, {%0,%1,%2,%3};"
        : "+f"(c[0]), "+f"(c[1]), "+f"(c[2]), "+f"(c[3])
        : "r"(a[0]), "r"(a[1]), "r"(a[2]), "r"(a[3]), "r"(b[0]), "r"(b[1]));
}

__device__ __forceinline__ void cp16(float* dst_s, const float* src_g, int sz) {
    uint32_t dst = (uint32_t)__cvta_generic_to_shared(dst_s);
    asm volatile("cp.async.cg.shared.global [%0], [%1], 16, %2;\n"
                 :: "r"(dst), "l"(src_g), "r"(sz));
}

// ---------------- tf32 tensor-core NT GEMM ----------------------------------
// C[m,n] = sum_k A[m,k] * B[n,k].  M must be a multiple of 128.
// MODE 0: C row-major [M,N].  MODE 1: head-split epilogue (M=B*S, N=H*HD).
template <int MODE>
__global__ __launch_bounds__(256) void gemm_tf32(
    const float* __restrict__ A, const float* __restrict__ Bm,
    float* __restrict__ C, int M, int N, int K,
    long long sA, long long sB, long long sC, int bmodB)
{
    extern __shared__ float smbuf[];
    const int z = blockIdx.z;
    A  += (long long)z * sA;
    Bm += (long long)(z % bmodB) * sB;
    C  += (long long)z * sC;

    const int bm = blockIdx.y * 128, bn = blockIdx.x * 128;
    const int tid = threadIdx.x;
    const int wid = tid >> 5, lane = tid & 31;
    const int wm = (wid & 3) * 32, wn = (wid >> 2) * 64;
    const int q = lane >> 2, t = lane & 3;

    const int lrow = tid >> 3;
    const int lcol = (tid & 7) * 4;

    float acc[2][8][4];
#pragma unroll
    for (int mi = 0; mi < 2; mi++)
#pragma unroll
        for (int ni = 0; ni < 8; ni++)
#pragma unroll
            for (int e = 0; e < 4; e++) acc[mi][ni][e] = 0.f;

    const int ktiles = K >> 5;

#define ISSUE(KT, STAGE)                                                      \
    {                                                                         \
        float* As = smbuf + (STAGE) * (2 * 128 * BKP);                        \
        float* Bs = As + 128 * BKP;                                           \
        int k0 = (KT) * 32;                                                   \
        _Pragma("unroll")                                                     \
        for (int rep = 0; rep < 4; rep++) {                                   \
            int row = rep * 32 + lrow;                                        \
            cp16(As + row * BKP + lcol,                                       \
                 A + (long long)(bm + row) * K + k0 + lcol, 16);              \
            int gb = bn + row;                                                \
            int gbc = gb < N ? gb : (N - 1);                                  \
            cp16(Bs + row * BKP + lcol,                                       \
                 Bm + (long long)gbc * K + k0 + lcol, (gb < N) ? 16 : 0);     \
        }                                                                     \
        asm volatile("cp.async.commit_group;\n");                             \
    }

    ISSUE(0, 0);

    for (int kt = 0; kt < ktiles; kt++) {
        if (kt + 1 < ktiles) {
            ISSUE(kt + 1, (kt + 1) & 1);
            asm volatile("cp.async.wait_group 1;\n");
        } else {
            asm volatile("cp.async.wait_group 0;\n");
        }
        __syncthreads();

        const float* As = smbuf + (kt & 1) * (2 * 128 * BKP);
        const float* Bs = As + 128 * BKP;
#pragma unroll
        for (int ks = 0; ks < 4; ks++) {
            const int kb = ks * 8;
            uint32_t af[2][4];
#pragma unroll
            for (int mi = 0; mi < 2; mi++) {
                int r0 = wm + mi * 16 + q;
                af[mi][0] = f2tf32(As[r0 * BKP + kb + t]);
                af[mi][1] = f2tf32(As[(r0 + 8) * BKP + kb + t]);
                af[mi][2] = f2tf32(As[r0 * BKP + kb + 4 + t]);
                af[mi][3] = f2tf32(As[(r0 + 8) * BKP + kb + 4 + t]);
            }
            uint32_t bf[8][2];
#pragma unroll
            for (int ni = 0; ni < 8; ni++) {
                int n0 = wn + ni * 8 + q;
                bf[ni][0] = f2tf32(Bs[n0 * BKP + kb + t]);
                bf[ni][1] = f2tf32(Bs[n0 * BKP + kb + 4 + t]);
            }
#pragma unroll
            for (int mi = 0; mi < 2; mi++)
#pragma unroll
                for (int ni = 0; ni < 8; ni++)
                    mma_tf32(acc[mi][ni], af[mi], bf[ni]);
        }
        __syncthreads();
    }
#undef ISSUE

#pragma unroll
    for (int mi = 0; mi < 2; mi++)
#pragma unroll
        for (int ni = 0; ni < 8; ni++) {
            int gr0 = bm + wm + mi * 16 + q;
            int gc0 = bn + wn + ni * 8 + t * 2;
#pragma unroll
            for (int e = 0; e < 4; e++) {
                int gr = gr0 + ((e >= 2) ? 8 : 0);
                int gc = gc0 + (e & 1);
                if (gc >= N) continue;
                float v = acc[mi][ni][e];
                if (MODE == 0) {
                    C[(long long)gr * N + gc] = v;
                } else {
                    int b = gr >> 11, s = gr & 2047;
                    int h = gc >> 6, hd = gc & 63;
                    C[(((long long)b * H_ + h) * SQ_ + s) * HD_ + hd] = v;
                }
            }
        }
}

// ---------------- E transpose: relT[h][p][d] = E[p*D + d*H + h] -------------
__global__ void transpose_E(const float* __restrict__ E, float* __restrict__ relT)
{
    int idx = blockIdx.x * blockDim.x + threadIdx.x;
    if (idx >= H_ * P_ * HD_) return;
    int h = idx / (P_ * HD_);
    int rem = idx % (P_ * HD_);
    int p = rem / HD_;
    int d = rem % HD_;
    relT[idx] = E[(long long)p * D_ + d * H_ + h];
}

// ---------------- banded flash attention (tf32 tensor cores) ----------------
// grid: (SQ/64, H, B). 256 threads = 8 warps: 4-way M split x 2-way key split.
__global__ __launch_bounds__(256) void attn_mma(
    const float* __restrict__ qh, const float* __restrict__ kh,
    const float* __restrict__ vh, const float* __restrict__ qrel,
    float* __restrict__ O)
{
    extern __shared__ float sm[];
    float* Qs   = sm;                 // [64][AST] tf32 bits, Q rows
    float* Ks   = Qs + 64 * AST;      // [64][AST] tf32 bits, K rows
    float* Vt   = Ks + 64 * AST;      // [64][AST] tf32 bits, V^T (Vt[c][k])
    float* Ps   = Vt + 64 * AST;      // [64][AST] tf32 bits, P rows
    float* redm = Ps + 64 * AST;      // [2][64]
    float* redl = redm + 128;         // [2][64]

    const int i0 = blockIdx.x * 64;
    const int h = blockIdx.y, b = blockIdx.z;
    const long long hb = (long long)(b * H_ + h);
    const float* qb = qh + hb * SQ_ * HD_;
    const float* kb = kh + hb * SK_ * HD_;
    const float* vb = vh + hb * SK_ * HD_;
    const float* qr = qrel + hb * SQ_ * P_;

    const int tid = threadIdx.x;
    const int wid = tid >> 5, lane = tid & 31;
    const int q = lane >> 2, t = lane & 3;
    const int wm = (wid & 3) * 16;     // row block of this warp
    const int wn = (wid >> 2) * 32;    // col block (keys / out dims)
    const int split = wid >> 2;
    const int r0 = wm + q, r1 = r0 + 8;

    // load Q tile, converting to tf32 at store
    for (int l = tid; l < 1024; l += 256) {
        int r = l >> 4, d4 = (l & 15) << 2;
        float4 v = *(const float4*)(qb + (long long)(i0 + r) * HD_ + d4);
        uint32_t* dst = (uint32_t*)(Qs + r * AST + d4);
        dst[0] = f2tf32(v.x); dst[1] = f2tf32(v.y);
        dst[2] = f2tf32(v.z); dst[3] = f2tf32(v.w);
    }

    float m_run[2] = {-1e30f, -1e30f};
    float l_run[2] = {0.f, 0.f};
    float oacc[4][4];
#pragma unroll
    for (int ni = 0; ni < 4; ni++)
#pragma unroll
        for (int e = 0; e < 4; e++) oacc[ni][e] = 0.f;

    int lo = i0 - RAD_;       if (lo < 0) lo = 0;
    int hi = i0 + 64 + RAD_;  if (hi > SK_) hi = SK_;
    __syncthreads();

    for (int j0 = lo; j0 < hi; j0 += 64) {
        // load K rows + V transposed (tf32 at store)
        for (int l = tid; l < 1024; l += 256) {
            int r = l >> 4, d4 = (l & 15) << 2;
            float4 kv = *(const float4*)(kb + (long long)(j0 + r) * HD_ + d4);
            uint32_t* kd = (uint32_t*)(Ks + r * AST + d4);
            kd[0] = f2tf32(kv.x); kd[1] = f2tf32(kv.y);
            kd[2] = f2tf32(kv.z); kd[3] = f2tf32(kv.w);
            float4 vv = *(const float4*)(vb + (long long)(j0 + r) * HD_ + d4);
            uint32_t* vt = (uint32_t*)Vt;
            vt[(d4 + 0) * AST + r] = f2tf32(vv.x);
            vt[(d4 + 1) * AST + r] = f2tf32(vv.y);
            vt[(d4 + 2) * AST + r] = f2tf32(vv.z);
            vt[(d4 + 3) * AST + r] = f2tf32(vv.w);
        }
        __syncthreads();

        // ---- S = Q K^T via mma ----
        float sacc[4][4];
#pragma unroll
        for (int ni = 0; ni < 4; ni++)
#pragma unroll
            for (int e = 0; e < 4; e++) sacc[ni][e] = 0.f;

        const uint32_t* QsU = (const uint32_t*)Qs;
        const uint32_t* KsU = (const uint32_t*)Ks;
#pragma unroll
        for (int ks = 0; ks < 8; ks++) {
            int kk = ks * 8;
            uint32_t af[4];
            af[0] = QsU[r0 * AST + kk + t];
            af[1] = QsU[r1 * AST + kk + t];
            af[2] = QsU[r0 * AST + kk + 4 + t];
            af[3] = QsU[r1 * AST + kk + 4 + t];
#pragma unroll
            for (int ni = 0; ni < 4; ni++) {
                int c0 = wn + ni * 8 + q;
                uint32_t bf[2];
                bf[0] = KsU[c0 * AST + kk + t];
                bf[1] = KsU[c0 * AST + kk + 4 + t];
                mma_tf32(sacc[ni], af, bf);
            }
        }

        // ---- epilogue: rel gather + mask + scale; local row max ----
        float mloc[2] = {-1e30f, -1e30f};
#pragma unroll
        for (int ni = 0; ni < 4; ni++)
#pragma unroll
            for (int e = 0; e < 4; e++) {
                int ri = e >> 1;
                int rl = ri ? r1 : r0;
                int c = wn + ni * 8 + t * 2 + (e & 1);
                int delta = (j0 + c) - (i0 + rl);
                float s = -1e30f;
                if (delta >= -RAD_ && delta <= RAD_) {
                    int pid = min(max(delta, -R_), R_) + R_;
                    s = (sacc[ni][e] +
                         __ldg(qr + (long long)(i0 + rl) * P_ + pid)) * 0.125f;
                }
                sacc[ni][e] = s;
                mloc[ri] = fmaxf(mloc[ri], s);
            }
#pragma unroll
        for (int i = 0; i < 2; i++) {
            mloc[i] = fmaxf(mloc[i], __shfl_xor_sync(0xffffffffu, mloc[i], 1));
            mloc[i] = fmaxf(mloc[i], __shfl_xor_sync(0xffffffffu, mloc[i], 2));
        }
        if (t == 0) {
            redm[split * 64 + r0] = mloc[0];
            redm[split * 64 + r1] = mloc[1];
        }
        __syncthreads();

        float mnew[2], f[2];
#pragma unroll
        for (int i = 0; i < 2; i++) {
            int rl = i ? r1 : r0;
            float mt = fmaxf(redm[rl], redm[64 + rl]);
            mnew[i] = fmaxf(m_run[i], mt);
            f[i] = __expf(m_run[i] - mnew[i]);
            m_run[i] = mnew[i];
        }

        // ---- exp, P -> smem (tf32), partial row sums ----
        uint32_t* PsU = (uint32_t*)Ps;
        float sloc[2] = {0.f, 0.f};
#pragma unroll
        for (int ni = 0; ni < 4; ni++)
#pragma unroll
            for (int e = 0; e < 4; e++) {
                int ri = e >> 1;
                int rl = ri ? r1 : r0;
                int c = wn + ni * 8 + t * 2 + (e & 1);
                float p = __expf(sacc[ni][e] - mnew[ri]);
                sloc[ri] += p;
                PsU[rl * AST + c] = f2tf32(p);
            }
#pragma unroll
        for (int i = 0; i < 2; i++) {
            sloc[i] += __shfl_xor_sync(0xffffffffu, sloc[i], 1);
            sloc[i] += __shfl_xor_sync(0xffffffffu, sloc[i], 2);
        }
        if (t == 0) {
            redl[split * 64 + r0] = sloc[0];
            redl[split * 64 + r1] = sloc[1];
        }
        __syncthreads();

#pragma unroll
        for (int i = 0; i < 2; i++) {
            int rl = i ? r1 : r0;
            l_run[i] = l_run[i] * f[i] + redl[rl] + redl[64 + rl];
        }
#pragma unroll
        for (int ni = 0; ni < 4; ni++)
#pragma unroll
            for (int e = 0; e < 4; e++) oacc[ni][e] *= f[e >> 1];

        // ---- O += P V via mma ----
        const uint32_t* PsC = (const uint32_t*)Ps;
        const uint32_t* VtC = (const uint32_t*)Vt;
#pragma unroll
        for (int ks = 0; ks < 8; ks++) {
            int kk = ks * 8;
            uint32_t af[4];
            af[0] = PsC[r0 * AST + kk + t];
            af[1] = PsC[r1 * AST + kk + t];
            af[2] = PsC[r0 * AST + kk + 4 + t];
            af[3] = PsC[r1 * AST + kk + 4 + t];
#pragma unroll
            for (int ni = 0; ni < 4; ni++) {
                int c0 = wn + ni * 8 + q;
                uint32_t bf[2];
                bf[0] = VtC[c0 * AST + kk + t];
                bf[1] = VtC[c0 * AST + kk + 4 + t];
                mma_tf32(oacc[ni], af, bf);
            }
        }
        __syncthreads();
    }

    // ---- normalize + write O[b][s][hd*H + h] ----
    float inv[2] = {1.f / l_run[0], 1.f / l_run[1]};
#pragma unroll
    for (int ni = 0; ni < 4; ni++)
#pragma unroll
        for (int e = 0; e < 4; e++) {
            int ri = e >> 1;
            int rl = ri ? r1 : r0;
            int c = wn + ni * 8 + t * 2 + (e & 1);
            O[((long long)b * SQ_ + i0 + rl) * D_ + c * H_ + h] =
                oacc[ni][e] * inv[ri];
        }
}

// ---------------- launch -----------------------------------------------------
extern "C" void kernel_launch(void* const* d_in, const int* in_sizes, int n_in,
                              void* d_out, int out_size)
{
    const float* Q  = (const float*)d_in[0];
    const float* K  = (const float*)d_in[1];
    const float* V  = (const float*)d_in[2];
    const float* Wq = (const float*)d_in[3];
    const float* Wk = (const float*)d_in[4];
    const float* Wv = (const float*)d_in[5];
    const float* Wo = (const float*)d_in[6];
    const float* E  = (const float*)d_in[7];
    float* out = (float*)d_out;

    float *qh, *kh, *vh, *relT, *qrel, *o;
    cudaGetSymbolAddress((void**)&qh,   g_qh);
    cudaGetSymbolAddress((void**)&kh,   g_kh);
    cudaGetSymbolAddress((void**)&vh,   g_vh);
    cudaGetSymbolAddress((void**)&relT, g_relT);
    cudaGetSymbolAddress((void**)&qrel, g_qrel);
    cudaGetSymbolAddress((void**)&o,    g_o);

    const int gemm_smem = 2 * 2 * 128 * BKP * (int)sizeof(float);
    cudaFuncSetAttribute(gemm_tf32<0>, cudaFuncAttributeMaxDynamicSharedMemorySize, gemm_smem);
    cudaFuncSetAttribute(gemm_tf32<1>, cudaFuncAttributeMaxDynamicSharedMemorySize, gemm_smem);

    dim3 blk(256);
    dim3 gproj(1024 / 128, 4096 / 128, 1);

    // transpose first (moves attention into ncu's -s 5 slot)
    int nE = H_ * P_ * HD_;
    transpose_E<<<(nE + 255) / 256, 256>>>(E, relT);

    gemm_tf32<1><<<gproj, blk, gemm_smem>>>(Q, Wq, qh, 4096, 1024, 1024, 0, 0, 0, 1);
    gemm_tf32<1><<<gproj, blk, gemm_smem>>>(K, Wk, kh, 4096, 1024, 1024, 0, 0, 0, 1);
    gemm_tf32<1><<<gproj, blk, gemm_smem>>>(V, Wv, vh, 4096, 1024, 1024, 0, 0, 0, 1);

    dim3 gqr((P_ + 127) / 128, SQ_ / 128, B_ * H_);
    gemm_tf32<0><<<gqr, blk, gemm_smem>>>(qh, relT, qrel, SQ_, P_, HD_,
                                          (long long)SQ_ * HD_, (long long)P_ * HD_,
                                          (long long)SQ_ * P_, H_);

    // banded attention (tensor cores)
    int asmem = (4 * 64 * AST + 256) * (int)sizeof(float);   // ~70.7 KB
    cudaFuncSetAttribute(attn_mma, cudaFuncAttributeMaxDynamicSharedMemorySize, asmem);
    dim3 gattn(SQ_ / 64, H_, B_);
    attn_mma<<<gattn, blk, asmem>>>(qh, kh, vh, qrel, o);

    gemm_tf32<0><<<gproj, blk, gemm_smem>>>(o, Wo, out, 4096, 1024, 1024, 0, 0, 0, 1);

    (void)in_sizes; (void)n_in; (void)out_size;
}

// round 4
// speedup vs baseline: 2.7450x; 1.1173x over previous
#include <cuda_runtime.h>
#include <cstdint>

#define B_   2
#define SQ_  2048
#define SK_  2048
#define D_   1024
#define H_   16
#define HD_  64
#define P_   257
#define R_   128
#define RAD_ 256

#define BKP 36   // padded K stride for tf32 gemm smem tiles
#define AST 68   // attention smem stride (68 % 32 == 4 -> conflict-free frags)

// ---------------- scratch (device globals; no allocation allowed) -----------
__device__ float g_qh[(size_t)B_ * H_ * SQ_ * HD_];     // tf32 bits
__device__ float g_kh[(size_t)B_ * H_ * SK_ * HD_];     // tf32 bits
__device__ float g_vh[(size_t)B_ * H_ * SK_ * HD_];     // tf32 bits
__device__ float g_relT[(size_t)H_ * P_ * HD_];         // tf32 bits
__device__ float g_qrel[(size_t)B_ * H_ * SQ_ * P_];    // fp32
__device__ float g_o[(size_t)B_ * SQ_ * D_];            // tf32 bits
__device__ float g_wbits[4 * (size_t)D_ * D_];          // tf32 bits of Wq,Wk,Wv,Wo

// ---------------- helpers ----------------------------------------------------
__device__ __forceinline__ uint32_t f2tf32(float x) {
    uint32_t r;
    asm("cvt.rna.tf32.f32 %0, %1;" : "=r"(r) : "f"(x));
    return r;
}

__device__ __forceinline__ void mma_tf32(float* c, const uint32_t* a, const uint32_t* b) {
    asm volatile(
        "mma.sync.aligned.m16n8k8.row.col.f32.tf32.tf32.f32 "
        "{%0,%1,%2,%3}, {%4,%5,%6,%7}, {%8,%9}, {%0,%1,%2,%3};"
        : "+f"(c[0]), "+f"(c[1]), "+f"(c[2]), "+f"(c[3])
        : "r"(a[0]), "r"(a[1]), "r"(a[2]), "r"(a[3]), "r"(b[0]), "r"(b[1]));
}

__device__ __forceinline__ void cp16(float* dst_s, const float* src_g, int sz) {
    uint32_t dst = (uint32_t)__cvta_generic_to_shared(dst_s);
    asm volatile("cp.async.cg.shared.global [%0], [%1], 16, %2;\n"
                 :: "r"(dst), "l"(src_g), "r"(sz));
}

// ---------------- weight pre-conversion -------------------------------------
__global__ void convert_tf32(const float* __restrict__ src, float* __restrict__ dst, int n4)
{
    int i = blockIdx.x * blockDim.x + threadIdx.x;
    if (i >= n4) return;
    float4 v = ((const float4*)src)[i];
    uint4 o;
    o.x = f2tf32(v.x); o.y = f2tf32(v.y); o.z = f2tf32(v.z); o.w = f2tf32(v.w);
    ((uint4*)dst)[i] = o;
}

// ---------------- tf32 tensor-core NT GEMM ----------------------------------
// C[m,n] = sum_k A[m,k] * B[n,k].  M multiple of 128.
// MODE 0: C row-major fp32.  MODE 1: head-split epilogue, stores tf32 bits.
// CVTA: convert A fragments from fp32 (else A already holds tf32 bits).
template <int MODE, int CVTA>
__global__ __launch_bounds__(256, 2) void gemm_tf32(
    const float* __restrict__ A, const float* __restrict__ Bm,
    float* __restrict__ C, int M, int N, int K,
    long long sA, long long sB, long long sC, int bmodB)
{
    extern __shared__ float smbuf[];
    const int z = blockIdx.z;
    A  += (long long)z * sA;
    Bm += (long long)(z % bmodB) * sB;
    C  += (long long)z * sC;

    const int bm = blockIdx.y * 128, bn = blockIdx.x * 128;
    const int tid = threadIdx.x;
    const int wid = tid >> 5, lane = tid & 31;
    const int wm = (wid & 3) * 32, wn = (wid >> 2) * 64;
    const int q = lane >> 2, t = lane & 3;

    const int lrow = tid >> 3;
    const int lcol = (tid & 7) * 4;

    float acc[2][8][4];
#pragma unroll
    for (int mi = 0; mi < 2; mi++)
#pragma unroll
        for (int ni = 0; ni < 8; ni++)
#pragma unroll
            for (int e = 0; e < 4; e++) acc[mi][ni][e] = 0.f;

    const int ktiles = K >> 5;

#define ISSUE(KT, STAGE)                                                      \
    {                                                                         \
        float* As = smbuf + (STAGE) * (2 * 128 * BKP);                        \
        float* Bs = As + 128 * BKP;                                           \
        int k0 = (KT) * 32;                                                   \
        _Pragma("unroll")                                                     \
        for (int rep = 0; rep < 4; rep++) {                                   \
            int row = rep * 32 + lrow;                                        \
            cp16(As + row * BKP + lcol,                                       \
                 A + (long long)(bm + row) * K + k0 + lcol, 16);              \
            int gb = bn + row;                                                \
            int gbc = gb < N ? gb : (N - 1);                                  \
            cp16(Bs + row * BKP + lcol,                                       \
                 Bm + (long long)gbc * K + k0 + lcol, (gb < N) ? 16 : 0);     \
        }                                                                     \
        asm volatile("cp.async.commit_group;\n");                             \
    }

    ISSUE(0, 0);

    for (int kt = 0; kt < ktiles; kt++) {
        if (kt + 1 < ktiles) {
            ISSUE(kt + 1, (kt + 1) & 1);
            asm volatile("cp.async.wait_group 1;\n");
        } else {
            asm volatile("cp.async.wait_group 0;\n");
        }
        __syncthreads();

        const float* As = smbuf + (kt & 1) * (2 * 128 * BKP);
        const float* Bs = As + 128 * BKP;
        const uint32_t* AsU = (const uint32_t*)As;
        const uint32_t* BsU = (const uint32_t*)Bs;
#pragma unroll
        for (int ks = 0; ks < 4; ks++) {
            const int kb = ks * 8;
            uint32_t af[2][4];
#pragma unroll
            for (int mi = 0; mi < 2; mi++) {
                int r0 = wm + mi * 16 + q;
                if (CVTA) {
                    af[mi][0] = f2tf32(As[r0 * BKP + kb + t]);
                    af[mi][1] = f2tf32(As[(r0 + 8) * BKP + kb + t]);
                    af[mi][2] = f2tf32(As[r0 * BKP + kb + 4 + t]);
                    af[mi][3] = f2tf32(As[(r0 + 8) * BKP + kb + 4 + t]);
                } else {
                    af[mi][0] = AsU[r0 * BKP + kb + t];
                    af[mi][1] = AsU[(r0 + 8) * BKP + kb + t];
                    af[mi][2] = AsU[r0 * BKP + kb + 4 + t];
                    af[mi][3] = AsU[(r0 + 8) * BKP + kb + 4 + t];
                }
            }
            uint32_t bf[8][2];
#pragma unroll
            for (int ni = 0; ni < 8; ni++) {
                int n0 = wn + ni * 8 + q;
                bf[ni][0] = BsU[n0 * BKP + kb + t];
                bf[ni][1] = BsU[n0 * BKP + kb + 4 + t];
            }
#pragma unroll
            for (int mi = 0; mi < 2; mi++)
#pragma unroll
                for (int ni = 0; ni < 8; ni++)
                    mma_tf32(acc[mi][ni], af[mi], bf[ni]);
        }
        __syncthreads();
    }
#undef ISSUE

#pragma unroll
    for (int mi = 0; mi < 2; mi++)
#pragma unroll
        for (int ni = 0; ni < 8; ni++) {
            int gr0 = bm + wm + mi * 16 + q;
            int gc0 = bn + wn + ni * 8 + t * 2;
#pragma unroll
            for (int e = 0; e < 4; e++) {
                int gr = gr0 + ((e >= 2) ? 8 : 0);
                int gc = gc0 + (e & 1);
                if (gc >= N) continue;
                float v = acc[mi][ni][e];
                if (MODE == 0) {
                    C[(long long)gr * N + gc] = v;
                } else {
                    int b = gr >> 11, s = gr & 2047;
                    int h = gc >> 6, hd = gc & 63;
                    C[(((long long)b * H_ + h) * SQ_ + s) * HD_ + hd] =
                        __uint_as_float(f2tf32(v));
                }
            }
        }
}

// ---------------- E transpose -> tf32 bits ----------------------------------
__global__ void transpose_E(const float* __restrict__ E, float* __restrict__ relT)
{
    int idx = blockIdx.x * blockDim.x + threadIdx.x;
    if (idx >= H_ * P_ * HD_) return;
    int h = idx / (P_ * HD_);
    int rem = idx % (P_ * HD_);
    int p = rem / HD_;
    int d = rem % HD_;
    relT[idx] = __uint_as_float(f2tf32(E[(long long)p * D_ + d * H_ + h]));
}

// ---------------- banded flash attention (tf32 tensor cores) ----------------
// qh/kh/vh hold tf32 bits already; loads are straight copies.
__global__ __launch_bounds__(256, 2) void attn_mma(
    const float* __restrict__ qh, const float* __restrict__ kh,
    const float* __restrict__ vh, const float* __restrict__ qrel,
    float* __restrict__ O)
{
    extern __shared__ float sm[];
    float* Qs   = sm;                 // [64][AST]
    float* Ks   = Qs + 64 * AST;      // [64][AST]
    float* Vt   = Ks + 64 * AST;      // [64][AST] V^T
    float* Ps   = Vt + 64 * AST;      // [64][AST]
    float* redm = Ps + 64 * AST;      // [2][64]
    float* redl = redm + 128;         // [2][64]

    const int i0 = blockIdx.x * 64;
    const int h = blockIdx.y, b = blockIdx.z;
    const long long hb = (long long)(b * H_ + h);
    const float* qb = qh + hb * SQ_ * HD_;
    const float* kb = kh + hb * SK_ * HD_;
    const float* vb = vh + hb * SK_ * HD_;
    const float* qr = qrel + hb * SQ_ * P_;

    const int tid = threadIdx.x;
    const int wid = tid >> 5, lane = tid & 31;
    const int q = lane >> 2, t = lane & 3;
    const int wm = (wid & 3) * 16;
    const int wn = (wid >> 2) * 32;
    const int split = wid >> 2;
    const int r0 = wm + q, r1 = r0 + 8;

    for (int l = tid; l < 1024; l += 256) {
        int r = l >> 4, d4 = (l & 15) << 2;
        float4 v = *(const float4*)(qb + (long long)(i0 + r) * HD_ + d4);
        *(float4*)(Qs + r * AST + d4) = v;
    }

    float m_run[2] = {-1e30f, -1e30f};
    float l_run[2] = {0.f, 0.f};
    float oacc[4][4];
#pragma unroll
    for (int ni = 0; ni < 4; ni++)
#pragma unroll
        for (int e = 0; e < 4; e++) oacc[ni][e] = 0.f;

    int lo = i0 - RAD_;       if (lo < 0) lo = 0;
    int hi = i0 + 64 + RAD_;  if (hi > SK_) hi = SK_;
    __syncthreads();

    for (int j0 = lo; j0 < hi; j0 += 64) {
        for (int l = tid; l < 1024; l += 256) {
            int r = l >> 4, d4 = (l & 15) << 2;
            float4 kv = *(const float4*)(kb + (long long)(j0 + r) * HD_ + d4);
            *(float4*)(Ks + r * AST + d4) = kv;
            float4 vv = *(const float4*)(vb + (long long)(j0 + r) * HD_ + d4);
            Vt[(d4 + 0) * AST + r] = vv.x;
            Vt[(d4 + 1) * AST + r] = vv.y;
            Vt[(d4 + 2) * AST + r] = vv.z;
            Vt[(d4 + 3) * AST + r] = vv.w;
        }
        __syncthreads();

        float sacc[4][4];
#pragma unroll
        for (int ni = 0; ni < 4; ni++)
#pragma unroll
            for (int e = 0; e < 4; e++) sacc[ni][e] = 0.f;

        const uint32_t* QsU = (const uint32_t*)Qs;
        const uint32_t* KsU = (const uint32_t*)Ks;
#pragma unroll
        for (int ks = 0; ks < 8; ks++) {
            int kk = ks * 8;
            uint32_t af[4];
            af[0] = QsU[r0 * AST + kk + t];
            af[1] = QsU[r1 * AST + kk + t];
            af[2] = QsU[r0 * AST + kk + 4 + t];
            af[3] = QsU[r1 * AST + kk + 4 + t];
#pragma unroll
            for (int ni = 0; ni < 4; ni++) {
                int c0 = wn + ni * 8 + q;
                uint32_t bf[2];
                bf[0] = KsU[c0 * AST + kk + t];
                bf[1] = KsU[c0 * AST + kk + 4 + t];
                mma_tf32(sacc[ni], af, bf);
            }
        }

        float mloc[2] = {-1e30f, -1e30f};
#pragma unroll
        for (int ni = 0; ni < 4; ni++)
#pragma unroll
            for (int e = 0; e < 4; e++) {
                int ri = e >> 1;
                int rl = ri ? r1 : r0;
                int c = wn + ni * 8 + t * 2 + (e & 1);
                int delta = (j0 + c) - (i0 + rl);
                float s = -1e30f;
                if (delta >= -RAD_ && delta <= RAD_) {
                    int pid = min(max(delta, -R_), R_) + R_;
                    s = (sacc[ni][e] +
                         __ldg(qr + (long long)(i0 + rl) * P_ + pid)) * 0.125f;
                }
                sacc[ni][e] = s;
                mloc[ri] = fmaxf(mloc[ri], s);
            }
#pragma unroll
        for (int i = 0; i < 2; i++) {
            mloc[i] = fmaxf(mloc[i], __shfl_xor_sync(0xffffffffu, mloc[i], 1));
            mloc[i] = fmaxf(mloc[i], __shfl_xor_sync(0xffffffffu, mloc[i], 2));
        }
        if (t == 0) {
            redm[split * 64 + r0] = mloc[0];
            redm[split * 64 + r1] = mloc[1];
        }
        __syncthreads();

        float mnew[2], f[2];
#pragma unroll
        for (int i = 0; i < 2; i++) {
            int rl = i ? r1 : r0;
            float mt = fmaxf(redm[rl], redm[64 + rl]);
            mnew[i] = fmaxf(m_run[i], mt);
            f[i] = __expf(m_run[i] - mnew[i]);
            m_run[i] = mnew[i];
        }

        uint32_t* PsU = (uint32_t*)Ps;
        float sloc[2] = {0.f, 0.f};
#pragma unroll
        for (int ni = 0; ni < 4; ni++)
#pragma unroll
            for (int e = 0; e < 4; e++) {
                int ri = e >> 1;
                int rl = ri ? r1 : r0;
                int c = wn + ni * 8 + t * 2 + (e & 1);
                float p = __expf(sacc[ni][e] - mnew[ri]);
                sloc[ri] += p;
                PsU[rl * AST + c] = f2tf32(p);
            }
#pragma unroll
        for (int i = 0; i < 2; i++) {
            sloc[i] += __shfl_xor_sync(0xffffffffu, sloc[i], 1);
            sloc[i] += __shfl_xor_sync(0xffffffffu, sloc[i], 2);
        }
        if (t == 0) {
            redl[split * 64 + r0] = sloc[0];
            redl[split * 64 + r1] = sloc[1];
        }
        __syncthreads();

#pragma unroll
        for (int i = 0; i < 2; i++) {
            int rl = i ? r1 : r0;
            l_run[i] = l_run[i] * f[i] + redl[rl] + redl[64 + rl];
        }
#pragma unroll
        for (int ni = 0; ni < 4; ni++)
#pragma unroll
            for (int e = 0; e < 4; e++) oacc[ni][e] *= f[e >> 1];

        const uint32_t* PsC = (const uint32_t*)Ps;
        const uint32_t* VtC = (const uint32_t*)Vt;
#pragma unroll
        for (int ks = 0; ks < 8; ks++) {
            int kk = ks * 8;
            uint32_t af[4];
            af[0] = PsC[r0 * AST + kk + t];
            af[1] = PsC[r1 * AST + kk + t];
            af[2] = PsC[r0 * AST + kk + 4 + t];
            af[3] = PsC[r1 * AST + kk + 4 + t];
#pragma unroll
            for (int ni = 0; ni < 4; ni++) {
                int c0 = wn + ni * 8 + q;
                uint32_t bf[2];
                bf[0] = VtC[c0 * AST + kk + t];
                bf[1] = VtC[c0 * AST + kk + 4 + t];
                mma_tf32(oacc[ni], af, bf);
            }
        }
        __syncthreads();
    }

    float inv[2] = {1.f / l_run[0], 1.f / l_run[1]};
#pragma unroll
    for (int ni = 0; ni < 4; ni++)
#pragma unroll
        for (int e = 0; e < 4; e++) {
            int ri = e >> 1;
            int rl = ri ? r1 : r0;
            int c = wn + ni * 8 + t * 2 + (e & 1);
            O[((long long)b * SQ_ + i0 + rl) * D_ + c * H_ + h] =
                __uint_as_float(f2tf32(oacc[ni][e] * inv[ri]));
        }
}

// ---------------- launch -----------------------------------------------------
extern "C" void kernel_launch(void* const* d_in, const int* in_sizes, int n_in,
                              void* d_out, int out_size)
{
    const float* Q  = (const float*)d_in[0];
    const float* K  = (const float*)d_in[1];
    const float* V  = (const float*)d_in[2];
    const float* Wq = (const float*)d_in[3];
    const float* Wk = (const float*)d_in[4];
    const float* Wv = (const float*)d_in[5];
    const float* Wo = (const float*)d_in[6];
    const float* E  = (const float*)d_in[7];
    float* out = (float*)d_out;

    float *qh, *kh, *vh, *relT, *qrel, *o, *wb;
    cudaGetSymbolAddress((void**)&qh,   g_qh);
    cudaGetSymbolAddress((void**)&kh,   g_kh);
    cudaGetSymbolAddress((void**)&vh,   g_vh);
    cudaGetSymbolAddress((void**)&relT, g_relT);
    cudaGetSymbolAddress((void**)&qrel, g_qrel);
    cudaGetSymbolAddress((void**)&o,    g_o);
    cudaGetSymbolAddress((void**)&wb,   g_wbits);

    const int gemm_smem = 2 * 2 * 128 * BKP * (int)sizeof(float);
    cudaFuncSetAttribute((const void*)gemm_tf32<0,0>, cudaFuncAttributeMaxDynamicSharedMemorySize, gemm_smem);
    cudaFuncSetAttribute((const void*)gemm_tf32<1,1>, cudaFuncAttributeMaxDynamicSharedMemorySize, gemm_smem);

    dim3 blk(256);
    dim3 gproj(1024 / 128, 4096 / 128, 1);

    // prologue conversions
    int nW4 = D_ * D_ / 4;
    convert_tf32<<<(nW4 + 255) / 256, 256>>>(Wq, wb + 0 * D_ * D_, nW4);
    convert_tf32<<<(nW4 + 255) / 256, 256>>>(Wk, wb + 1 * D_ * D_, nW4);
    convert_tf32<<<(nW4 + 255) / 256, 256>>>(Wv, wb + 2 * D_ * D_, nW4);
    convert_tf32<<<(nW4 + 255) / 256, 256>>>(Wo, wb + 3 * D_ * D_, nW4);
    int nE = H_ * P_ * HD_;
    transpose_E<<<(nE + 255) / 256, 256>>>(E, relT);

    // projections (A fp32 cvt in-loop, B pre-converted), outputs = tf32 bits
    gemm_tf32<1,1><<<gproj, blk, gemm_smem>>>(Q, wb + 0 * D_ * D_, qh, 4096, 1024, 1024, 0, 0, 0, 1);
    gemm_tf32<1,1><<<gproj, blk, gemm_smem>>>(K, wb + 1 * D_ * D_, kh, 4096, 1024, 1024, 0, 0, 0, 1);
    gemm_tf32<1,1><<<gproj, blk, gemm_smem>>>(V, wb + 2 * D_ * D_, vh, 4096, 1024, 1024, 0, 0, 0, 1);

    // Q_rel: both operands already tf32 bits
    dim3 gqr((P_ + 127) / 128, SQ_ / 128, B_ * H_);
    gemm_tf32<0,0><<<gqr, blk, gemm_smem>>>(qh, relT, qrel, SQ_, P_, HD_,
                                            (long long)SQ_ * HD_, (long long)P_ * HD_,
                                            (long long)SQ_ * P_, H_);

    // banded attention (all operands bits; o stored as bits)
    int asmem = (4 * 64 * AST + 256) * (int)sizeof(float);
    cudaFuncSetAttribute(attn_mma, cudaFuncAttributeMaxDynamicSharedMemorySize, asmem);
    dim3 gattn(SQ_ / 64, H_, B_);
    attn_mma<<<gattn, blk, asmem>>>(qh, kh, vh, qrel, o);

    // output projection: both operands bits
    gemm_tf32<0,0><<<gproj, blk, gemm_smem>>>(o, wb + 3 * D_ * D_, out, 4096, 1024, 1024, 0, 0, 0, 1);

    (void)in_sizes; (void)n_in; (void)out_size;
}

// round 6
// speedup vs baseline: 4.2129x; 1.5347x over previous
#include <cuda_runtime.h>
#include <cuda_fp16.h>
#include <cstdint>

#define B_   2
#define SQ_  2048
#define SK_  2048
#define D_   1024
#define H_   16
#define HD_  64
#define P_   257
#define R_   128
#define RAD_ 256

#define GST 36   // gemm smem row stride in uint32 (fp16x2) units
#define AST 36   // attention smem row stride in uint32 units

// ---------------- scratch (device globals; no allocation allowed) -----------
__device__ __half g_xf[3][(size_t)B_ * SQ_ * D_];       // fp16 inputs Q,K,V
__device__ __half g_wh[4][(size_t)D_ * D_];             // fp16 weights
__device__ __half g_qh[(size_t)B_ * H_ * SQ_ * HD_];
__device__ __half g_kh[(size_t)B_ * H_ * SK_ * HD_];
__device__ __half g_vh[(size_t)B_ * H_ * SK_ * HD_];
__device__ __half g_relT[(size_t)H_ * P_ * HD_];
__device__ float  g_qrel[(size_t)B_ * H_ * SQ_ * P_];
__device__ __half g_o[(size_t)B_ * SQ_ * D_];

// ---------------- helpers ----------------------------------------------------
__device__ __forceinline__ void mma_h(float* c, const uint32_t* a, const uint32_t* b) {
    asm volatile(
        "mma.sync.aligned.m16n8k16.row.col.f32.f16.f16.f32 "
        "{%0,%1,%2,%3}, {%4,%5,%6,%7}, {%8,%9}, {%0,%1,%2,%3};"
        : "+f"(c[0]), "+f"(c[1]), "+f"(c[2]), "+f"(c[3])
        : "r"(a[0]), "r"(a[1]), "r"(a[2]), "r"(a[3]), "r"(b[0]), "r"(b[1]));
}

__device__ __forceinline__ void cp16(void* dst_s, const void* src_g, int sz) {
    uint32_t dst = (uint32_t)__cvta_generic_to_shared(dst_s);
    asm volatile("cp.async.cg.shared.global [%0], [%1], 16, %2;\n"
                 :: "r"(dst), "l"(src_g), "r"(sz));
}

__device__ __forceinline__ uint32_t packh2(float x, float y) {
    __half2 h = __floats2half2_rn(x, y);
    return *(uint32_t*)&h;
}

// ---------------- prologue conversions ---------------------------------------
__global__ void cvt_qkv(const float* __restrict__ Q, const float* __restrict__ K,
                        const float* __restrict__ V, __half* __restrict__ qf,
                        __half* __restrict__ kf, __half* __restrict__ vf, int n4)
{
    int i = blockIdx.x * blockDim.x + threadIdx.x;
    if (i >= n4) return;
    float4 a = ((const float4*)Q)[i];
    ((uint2*)qf)[i] = make_uint2(packh2(a.x, a.y), packh2(a.z, a.w));
    float4 b = ((const float4*)K)[i];
    ((uint2*)kf)[i] = make_uint2(packh2(b.x, b.y), packh2(b.z, b.w));
    float4 c = ((const float4*)V)[i];
    ((uint2*)vf)[i] = make_uint2(packh2(c.x, c.y), packh2(c.z, c.w));
}

__global__ void cvt_w(const float* __restrict__ w0, const float* __restrict__ w1,
                      const float* __restrict__ w2, const float* __restrict__ w3,
                      __half* __restrict__ dst, int n4)
{
    int i = blockIdx.x * blockDim.x + threadIdx.x;
    if (i >= n4) return;
    const float* srcs[4] = {w0, w1, w2, w3};
#pragma unroll
    for (int m = 0; m < 4; m++) {
        float4 a = ((const float4*)srcs[m])[i];
        ((uint2*)(dst + (size_t)m * D_ * D_))[i] =
            make_uint2(packh2(a.x, a.y), packh2(a.z, a.w));
    }
}

__global__ void transpose_E(const float* __restrict__ E, __half* __restrict__ relT)
{
    int idx = blockIdx.x * blockDim.x + threadIdx.x;
    if (idx >= H_ * P_ * HD_) return;
    int h = idx / (P_ * HD_);
    int rem = idx % (P_ * HD_);
    int p = rem / HD_;
    int d = rem % HD_;
    relT[idx] = __float2half(E[(long long)p * D_ + d * H_ + h]);
}

// ---------------- fp16 tensor-core NT GEMM ----------------------------------
// C[m,n] = sum_k A[m,k]*B[n,k]. M multiple of 128. K multiple of 64.
// MODE 0: C fp32 row-major.  MODE 1: head-split epilogue, C fp16.
template <int MODE>
__global__ __launch_bounds__(256, 2) void gemm_h(
    const __half* __restrict__ A, const __half* __restrict__ Bm,
    void* __restrict__ Cv, int M, int N, int K,
    long long sA, long long sB, long long sC, int bmodB)
{
    extern __shared__ uint32_t smh[];   // 2 stages * 2 * 128 * GST
    const int z = blockIdx.z;
    A  += (long long)z * sA;
    Bm += (long long)(z % bmodB) * sB;
    float* Cf = (float*)Cv + (MODE == 0 ? (long long)z * sC : 0);
    __half* Ch = (__half*)Cv;

    const int bm = blockIdx.y * 128, bn = blockIdx.x * 128;
    const int tid = threadIdx.x;
    const int wid = tid >> 5, lane = tid & 31;
    const int wm = (wid & 3) * 32, wn = (wid >> 2) * 64;
    const int q = lane >> 2, t = lane & 3;

    float acc[2][8][4];
#pragma unroll
    for (int mi = 0; mi < 2; mi++)
#pragma unroll
        for (int ni = 0; ni < 8; ni++)
#pragma unroll
            for (int e = 0; e < 4; e++) acc[mi][ni][e] = 0.f;

    const int ktiles = K >> 6;

#define ISSUE(KT, STAGE)                                                      \
    {                                                                         \
        uint32_t* As = smh + (STAGE) * (2 * 128 * GST);                       \
        uint32_t* Bs = As + 128 * GST;                                        \
        int k0 = (KT) * 64;                                                   \
        _Pragma("unroll")                                                     \
        for (int rep = 0; rep < 4; rep++) {                                   \
            int idx = rep * 256 + tid;                                        \
            int row = idx >> 3, ch = idx & 7;                                 \
            cp16(As + row * GST + ch * 4,                                     \
                 A + (long long)(bm + row) * K + k0 + ch * 8, 16);            \
            int gb = bn + row;                                                \
            int gbc = gb < N ? gb : (N - 1);                                  \
            cp16(Bs + row * GST + ch * 4,                                     \
                 Bm + (long long)gbc * K + k0 + ch * 8, (gb < N) ? 16 : 0);   \
        }                                                                     \
        asm volatile("cp.async.commit_group;\n");                             \
    }

    ISSUE(0, 0);

    for (int kt = 0; kt < ktiles; kt++) {
        if (kt + 1 < ktiles) {
            ISSUE(kt + 1, (kt + 1) & 1);
            asm volatile("cp.async.wait_group 1;\n");
        } else {
            asm volatile("cp.async.wait_group 0;\n");
        }
        __syncthreads();

        const uint32_t* As = smh + (kt & 1) * (2 * 128 * GST);
        const uint32_t* Bs = As + 128 * GST;
#pragma unroll
        for (int ks = 0; ks < 4; ks++) {
            const int kb = ks * 8;
            uint32_t af[2][4];
#pragma unroll
            for (int mi = 0; mi < 2; mi++) {
                int r0 = wm + mi * 16 + q;
                af[mi][0] = As[r0 * GST + kb + t];
                af[mi][1] = As[(r0 + 8) * GST + kb + t];
                af[mi][2] = As[r0 * GST + kb + 4 + t];
                af[mi][3] = As[(r0 + 8) * GST + kb + 4 + t];
            }
            uint32_t bf[8][2];
#pragma unroll
            for (int ni = 0; ni < 8; ni++) {
                int n0 = wn + ni * 8 + q;
                bf[ni][0] = Bs[n0 * GST + kb + t];
                bf[ni][1] = Bs[n0 * GST + kb + 4 + t];
            }
#pragma unroll
            for (int mi = 0; mi < 2; mi++)
#pragma unroll
                for (int ni = 0; ni < 8; ni++)
                    mma_h(acc[mi][ni], af[mi], bf[ni]);
        }
        __syncthreads();
    }
#undef ISSUE

#pragma unroll
    for (int mi = 0; mi < 2; mi++)
#pragma unroll
        for (int ni = 0; ni < 8; ni++) {
            int gr0 = bm + wm + mi * 16 + q;
            int gc0 = bn + wn + ni * 8 + t * 2;
#pragma unroll
            for (int e = 0; e < 4; e++) {
                int gr = gr0 + ((e >= 2) ? 8 : 0);
                int gc = gc0 + (e & 1);
                if (gc >= N) continue;
                float v = acc[mi][ni][e];
                if (MODE == 0) {
                    Cf[(long long)gr * N + gc] = v;
                } else {
                    int b = gr >> 11, s = gr & 2047;
                    int h = gc >> 6, hd = gc & 63;
                    Ch[(((long long)b * H_ + h) * SQ_ + s) * HD_ + hd] = __float2half(v);
                }
            }
        }
}

// ---------------- banded flash attention (fp16 tensor cores) ----------------
__global__ __launch_bounds__(256, 2) void attn_mma(
    const __half* __restrict__ qh, const __half* __restrict__ kh,
    const __half* __restrict__ vh, const float* __restrict__ qrel,
    __half* __restrict__ O)
{
    extern __shared__ uint32_t sma[];
    uint32_t* Qs = sma;                 // [64][AST]
    uint32_t* Ks = Qs + 64 * AST;
    uint32_t* Vt = Ks + 64 * AST;       // Vt[dim][key-pair]
    uint32_t* Ps = Vt + 64 * AST;
    float* redm = (float*)(Ps + 64 * AST);   // [2][64]
    float* redl = redm + 128;                // [2][64]

    const int i0 = blockIdx.x * 64;
    const int h = blockIdx.y, b = blockIdx.z;
    const long long hb = (long long)(b * H_ + h);
    const uint32_t* qb = (const uint32_t*)(qh + hb * SQ_ * HD_);
    const uint32_t* kb = (const uint32_t*)(kh + hb * SK_ * HD_);
    const uint32_t* vb = (const uint32_t*)(vh + hb * SK_ * HD_);
    const float* qr = qrel + hb * SQ_ * P_;

    const int tid = threadIdx.x;
    const int wid = tid >> 5, lane = tid & 31;
    const int q = lane >> 2, t = lane & 3;
    const int wm = (wid & 3) * 16;
    const int wn = (wid >> 2) * 32;
    const int split = wid >> 2;
    const int r0 = wm + q, r1 = r0 + 8;

    // Q tile: rows of 32 uint32 (64 fp16)
#pragma unroll
    for (int l = tid; l < 512; l += 256) {
        int r = l >> 3, ch = l & 7;
        *(uint4*)(Qs + r * AST + ch * 4) =
            *(const uint4*)(qb + (long long)(i0 + r) * 32 + ch * 4);
    }

    float m_run[2] = {-1e30f, -1e30f};
    float l_run[2] = {0.f, 0.f};
    float oacc[4][4];
#pragma unroll
    for (int ni = 0; ni < 4; ni++)
#pragma unroll
        for (int e = 0; e < 4; e++) oacc[ni][e] = 0.f;

    int lo = i0 - RAD_;       if (lo < 0) lo = 0;
    int hi = i0 + 64 + RAD_;  if (hi > SK_) hi = SK_;
    __syncthreads();

    for (int j0 = lo; j0 < hi; j0 += 64) {
        // K rows
#pragma unroll
        for (int l = tid; l < 512; l += 256) {
            int r = l >> 3, ch = l & 7;
            *(uint4*)(Ks + r * AST + ch * 4) =
                *(const uint4*)(kb + (long long)(j0 + r) * 32 + ch * 4);
        }
        // V transposed + key-pair packed: Vt[dim][kp] = {V[2kp][dim], V[2kp+1][dim]}
#pragma unroll
        for (int l = tid; l < 1024; l += 256) {
            int kp = l >> 5, n2 = l & 31;
            const uint32_t* vrow = vb + (long long)(j0 + 2 * kp) * 32;
            uint32_t a = vrow[n2];
            uint32_t c = vrow[32 + n2];
            Vt[(2 * n2) * AST + kp]     = __byte_perm(a, c, 0x5410);
            Vt[(2 * n2 + 1) * AST + kp] = __byte_perm(a, c, 0x7632);
        }
        __syncthreads();

        // ---- S = Q K^T ----
        float sacc[4][4];
#pragma unroll
        for (int ni = 0; ni < 4; ni++)
#pragma unroll
            for (int e = 0; e < 4; e++) sacc[ni][e] = 0.f;
#pragma unroll
        for (int ks = 0; ks < 4; ks++) {
            int kb2 = ks * 8;
            uint32_t af[4];
            af[0] = Qs[r0 * AST + kb2 + t];
            af[1] = Qs[r1 * AST + kb2 + t];
            af[2] = Qs[r0 * AST + kb2 + 4 + t];
            af[3] = Qs[r1 * AST + kb2 + 4 + t];
#pragma unroll
            for (int ni = 0; ni < 4; ni++) {
                int c0 = wn + ni * 8 + q;
                uint32_t bf[2];
                bf[0] = Ks[c0 * AST + kb2 + t];
                bf[1] = Ks[c0 * AST + kb2 + 4 + t];
                mma_h(sacc[ni], af, bf);
            }
        }

        // ---- rel gather + mask + scale; row max ----
        float mloc[2] = {-1e30f, -1e30f};
#pragma unroll
        for (int ni = 0; ni < 4; ni++)
#pragma unroll
            for (int e = 0; e < 4; e++) {
                int ri = e >> 1;
                int rl = ri ? r1 : r0;
                int c = wn + ni * 8 + t * 2 + (e & 1);
                int delta = (j0 + c) - (i0 + rl);
                float s = -1e30f;
                if (delta >= -RAD_ && delta <= RAD_) {
                    int pid = min(max(delta, -R_), R_) + R_;
                    s = (sacc[ni][e] +
                         __ldg(qr + (long long)(i0 + rl) * P_ + pid)) * 0.125f;
                }
                sacc[ni][e] = s;
                mloc[ri] = fmaxf(mloc[ri], s);
            }
#pragma unroll
        for (int i = 0; i < 2; i++) {
            mloc[i] = fmaxf(mloc[i], __shfl_xor_sync(0xffffffffu, mloc[i], 1));
            mloc[i] = fmaxf(mloc[i], __shfl_xor_sync(0xffffffffu, mloc[i], 2));
        }
        if (t == 0) {
            redm[split * 64 + r0] = mloc[0];
            redm[split * 64 + r1] = mloc[1];
        }
        __syncthreads();

        float mnew[2], f[2];
#pragma unroll
        for (int i = 0; i < 2; i++) {
            int rl = i ? r1 : r0;
            float mt = fmaxf(redm[rl], redm[64 + rl]);
            mnew[i] = fmaxf(m_run[i], mt);
            f[i] = __expf(m_run[i] - mnew[i]);
            m_run[i] = mnew[i];
        }

        // ---- exp, pack P to fp16 pairs, partial sums ----
        float sloc[2] = {0.f, 0.f};
#pragma unroll
        for (int ni = 0; ni < 4; ni++)
#pragma unroll
            for (int ri = 0; ri < 2; ri++) {
                int rl = ri ? r1 : r0;
                float p0 = __expf(sacc[ni][ri * 2 + 0] - mnew[ri]);
                float p1 = __expf(sacc[ni][ri * 2 + 1] - mnew[ri]);
                sloc[ri] += p0 + p1;
                Ps[rl * AST + wn / 2 + ni * 4 + t] = packh2(p0, p1);
            }
#pragma unroll
        for (int i = 0; i < 2; i++) {
            sloc[i] += __shfl_xor_sync(0xffffffffu, sloc[i], 1);
            sloc[i] += __shfl_xor_sync(0xffffffffu, sloc[i], 2);
        }
        if (t == 0) {
            redl[split * 64 + r0] = sloc[0];
            redl[split * 64 + r1] = sloc[1];
        }
        __syncthreads();

#pragma unroll
        for (int i = 0; i < 2; i++) {
            int rl = i ? r1 : r0;
            l_run[i] = l_run[i] * f[i] + redl[rl] + redl[64 + rl];
        }
#pragma unroll
        for (int ni = 0; ni < 4; ni++)
#pragma unroll
            for (int e = 0; e < 4; e++) oacc[ni][e] *= f[e >> 1];

        // ---- O += P V ----
#pragma unroll
        for (int ks = 0; ks < 4; ks++) {
            int kb2 = ks * 8;
            uint32_t af[4];
            af[0] = Ps[r0 * AST + kb2 + t];
            af[1] = Ps[r1 * AST + kb2 + t];
            af[2] = Ps[r0 * AST + kb2 + 4 + t];
            af[3] = Ps[r1 * AST + kb2 + 4 + t];
#pragma unroll
            for (int ni = 0; ni < 4; ni++) {
                int c0 = wn + ni * 8 + q;
                uint32_t bf[2];
                bf[0] = Vt[c0 * AST + kb2 + t];
                bf[1] = Vt[c0 * AST + kb2 + 4 + t];
                mma_h(oacc[ni], af, bf);
            }
        }
        __syncthreads();
    }

    // ---- normalize + store O[b][s][hd*H + h] as fp16 ----
    float inv[2] = {1.f / l_run[0], 1.f / l_run[1]};
#pragma unroll
    for (int ni = 0; ni < 4; ni++)
#pragma unroll
        for (int e = 0; e < 4; e++) {
            int ri = e >> 1;
            int rl = ri ? r1 : r0;
            int c = wn + ni * 8 + t * 2 + (e & 1);
            O[((long long)b * SQ_ + i0 + rl) * D_ + c * H_ + h] =
                __float2half(oacc[ni][e] * inv[ri]);
        }
}

// ---------------- launch -----------------------------------------------------
extern "C" void kernel_launch(void* const* d_in, const int* in_sizes, int n_in,
                              void* d_out, int out_size)
{
    const float* Q  = (const float*)d_in[0];
    const float* K  = (const float*)d_in[1];
    const float* V  = (const float*)d_in[2];
    const float* Wq = (const float*)d_in[3];
    const float* Wk = (const float*)d_in[4];
    const float* Wv = (const float*)d_in[5];
    const float* Wo = (const float*)d_in[6];
    const float* E  = (const float*)d_in[7];
    float* out = (float*)d_out;

    __half *xf, *wh, *qh, *kh, *vh, *relT, *o;
    float *qrel;
    cudaGetSymbolAddress((void**)&xf,   g_xf);
    cudaGetSymbolAddress((void**)&wh,   g_wh);
    cudaGetSymbolAddress((void**)&qh,   g_qh);
    cudaGetSymbolAddress((void**)&kh,   g_kh);
    cudaGetSymbolAddress((void**)&vh,   g_vh);
    cudaGetSymbolAddress((void**)&relT, g_relT);
    cudaGetSymbolAddress((void**)&qrel, g_qrel);
    cudaGetSymbolAddress((void**)&o,    g_o);

    __half* qf = xf + 0 * (size_t)B_ * SQ_ * D_;
    __half* kf = xf + 1 * (size_t)B_ * SQ_ * D_;
    __half* vf = xf + 2 * (size_t)B_ * SQ_ * D_;

    const int gemm_smem = 2 * 2 * 128 * GST * (int)sizeof(uint32_t);   // 73728
    cudaFuncSetAttribute((const void*)gemm_h<0>, cudaFuncAttributeMaxDynamicSharedMemorySize, gemm_smem);
    cudaFuncSetAttribute((const void*)gemm_h<1>, cudaFuncAttributeMaxDynamicSharedMemorySize, gemm_smem);

    dim3 blk(256);
    dim3 gproj(1024 / 128, 4096 / 128, 1);

    // prologue conversions
    int nx4 = B_ * SQ_ * D_ / 4;
    cvt_qkv<<<(nx4 + 255) / 256, 256>>>(Q, K, V, qf, kf, vf, nx4);
    int nW4 = D_ * D_ / 4;
    cvt_w<<<(nW4 + 255) / 256, 256>>>(Wq, Wk, Wv, Wo, wh, nW4);
    int nE = H_ * P_ * HD_;
    transpose_E<<<(nE + 255) / 256, 256>>>(E, relT);

    // projections -> head-split fp16
    gemm_h<1><<<gproj, blk, gemm_smem>>>(qf, wh + 0 * (size_t)D_ * D_, qh, 4096, 1024, 1024, 0, 0, 0, 1);
    gemm_h<1><<<gproj, blk, gemm_smem>>>(kf, wh + 1 * (size_t)D_ * D_, kh, 4096, 1024, 1024, 0, 0, 0, 1);
    gemm_h<1><<<gproj, blk, gemm_smem>>>(vf, wh + 2 * (size_t)D_ * D_, vh, 4096, 1024, 1024, 0, 0, 0, 1);

    // Q_rel (K=64, one k-tile)
    dim3 gqr((P_ + 127) / 128, SQ_ / 128, B_ * H_);
    gemm_h<0><<<gqr, blk, gemm_smem>>>(qh, relT, qrel, SQ_, P_, HD_,
                                       (long long)SQ_ * HD_, (long long)P_ * HD_,
                                       (long long)SQ_ * P_, H_);

    // banded attention
    int asmem = 4 * 64 * AST * (int)sizeof(uint32_t) + 256 * (int)sizeof(float);  // ~37.9 KB
    dim3 gattn(SQ_ / 64, H_, B_);
    attn_mma<<<gattn, blk, asmem>>>(qh, kh, vh, qrel, o);

    // output projection -> fp32 out
    gemm_h<0><<<gproj, blk, gemm_smem>>>(o, wh + 3 * (size_t)D_ * D_, out, 4096, 1024, 1024, 0, 0, 0, 1);

    (void)in_sizes; (void)n_in; (void)out_size;
}

// round 7
// speedup vs baseline: 4.6447x; 1.1025x over previous
#include <cuda_runtime.h>
#include <cuda_fp16.h>
#include <cstdint>

#define B_   2
#define SQ_  2048
#define SK_  2048
#define D_   1024
#define H_   16
#define HD_  64
#define P_   257
#define R_   128
#define RAD_ 256

#define GST 36   // gemm smem row stride in uint32 (fp16x2) units
#define AST 36   // attention smem row stride in uint32 units
#define ATILE (64 * AST)   // uint32s per 64-row attention tile

// ---------------- scratch (device globals; no allocation allowed) -----------
__device__ __half g_xf[3][(size_t)B_ * SQ_ * D_];       // fp16 inputs Q,K,V
__device__ __half g_wh[4][(size_t)D_ * D_];             // fp16 weights
__device__ __half g_qh[(size_t)B_ * H_ * SQ_ * HD_];
__device__ __half g_kh[(size_t)B_ * H_ * SK_ * HD_];
__device__ __half g_vh[(size_t)B_ * H_ * SK_ * HD_];
__device__ __half g_relT[(size_t)H_ * P_ * HD_];
__device__ float  g_qrel[(size_t)B_ * H_ * SQ_ * P_];
__device__ __half g_o[(size_t)B_ * SQ_ * D_];

// ---------------- helpers ----------------------------------------------------
__device__ __forceinline__ void mma_h(float* c, const uint32_t* a, const uint32_t* b) {
    asm volatile(
        "mma.sync.aligned.m16n8k16.row.col.f32.f16.f16.f32 "
        "{%0,%1,%2,%3}, {%4,%5,%6,%7}, {%8,%9}, {%0,%1,%2,%3};"
        : "+f"(c[0]), "+f"(c[1]), "+f"(c[2]), "+f"(c[3])
        : "r"(a[0]), "r"(a[1]), "r"(a[2]), "r"(a[3]), "r"(b[0]), "r"(b[1]));
}

__device__ __forceinline__ void ldsm4(uint32_t* r, uint32_t saddr) {
    asm volatile("ldmatrix.sync.aligned.m8n8.x4.shared.b16 {%0,%1,%2,%3}, [%4];"
                 : "=r"(r[0]), "=r"(r[1]), "=r"(r[2]), "=r"(r[3]) : "r"(saddr));
}

__device__ __forceinline__ void ldsm4t(uint32_t* r, uint32_t saddr) {
    asm volatile("ldmatrix.sync.aligned.m8n8.x4.trans.shared.b16 {%0,%1,%2,%3}, [%4];"
                 : "=r"(r[0]), "=r"(r[1]), "=r"(r[2]), "=r"(r[3]) : "r"(saddr));
}

__device__ __forceinline__ void stsm4(uint32_t saddr, uint32_t r0, uint32_t r1,
                                      uint32_t r2, uint32_t r3) {
    asm volatile("stmatrix.sync.aligned.m8n8.x4.shared.b16 [%0], {%1,%2,%3,%4};"
                 :: "r"(saddr), "r"(r0), "r"(r1), "r"(r2), "r"(r3) : "memory");
}

__device__ __forceinline__ void cp16(void* dst_s, const void* src_g, int sz) {
    uint32_t dst = (uint32_t)__cvta_generic_to_shared(dst_s);
    asm volatile("cp.async.cg.shared.global [%0], [%1], 16, %2;\n"
                 :: "r"(dst), "l"(src_g), "r"(sz));
}

__device__ __forceinline__ uint32_t s2u(const void* p) {
    return (uint32_t)__cvta_generic_to_shared(p);
}

__device__ __forceinline__ uint32_t packh2(float x, float y) {
    __half2 h = __floats2half2_rn(x, y);
    return *(uint32_t*)&h;
}

// ---------------- prologue conversions ---------------------------------------
__global__ void cvt_qkv(const float* __restrict__ Q, const float* __restrict__ K,
                        const float* __restrict__ V, __half* __restrict__ qf,
                        __half* __restrict__ kf, __half* __restrict__ vf, int n4)
{
    int i = blockIdx.x * blockDim.x + threadIdx.x;
    if (i >= n4) return;
    float4 a = ((const float4*)Q)[i];
    ((uint2*)qf)[i] = make_uint2(packh2(a.x, a.y), packh2(a.z, a.w));
    float4 b = ((const float4*)K)[i];
    ((uint2*)kf)[i] = make_uint2(packh2(b.x, b.y), packh2(b.z, b.w));
    float4 c = ((const float4*)V)[i];
    ((uint2*)vf)[i] = make_uint2(packh2(c.x, c.y), packh2(c.z, c.w));
}

__global__ void cvt_w(const float* __restrict__ w0, const float* __restrict__ w1,
                      const float* __restrict__ w2, const float* __restrict__ w3,
                      __half* __restrict__ dst, int n4)
{
    int i = blockIdx.x * blockDim.x + threadIdx.x;
    if (i >= n4) return;
    const float* srcs[4] = {w0, w1, w2, w3};
#pragma unroll
    for (int m = 0; m < 4; m++) {
        float4 a = ((const float4*)srcs[m])[i];
        ((uint2*)(dst + (size_t)m * D_ * D_))[i] =
            make_uint2(packh2(a.x, a.y), packh2(a.z, a.w));
    }
}

__global__ void transpose_E(const float* __restrict__ E, __half* __restrict__ relT)
{
    int idx = blockIdx.x * blockDim.x + threadIdx.x;
    if (idx >= H_ * P_ * HD_) return;
    int h = idx / (P_ * HD_);
    int rem = idx % (P_ * HD_);
    int p = rem / HD_;
    int d = rem % HD_;
    relT[idx] = __float2half(E[(long long)p * D_ + d * H_ + h]);
}

// ---------------- fp16 tensor-core NT GEMM (ldmatrix) ------------------------
template <int MODE>
__global__ __launch_bounds__(256, 2) void gemm_h(
    const __half* __restrict__ A, const __half* __restrict__ Bm,
    void* __restrict__ Cv, int M, int N, int K,
    long long sA, long long sB, long long sC, int bmodB)
{
    extern __shared__ uint32_t smh[];   // 2 stages * 2 * 128 * GST
    const int z = blockIdx.z;
    A  += (long long)z * sA;
    Bm += (long long)(z % bmodB) * sB;
    float* Cf = (float*)Cv + (MODE == 0 ? (long long)z * sC : 0);
    __half* Ch = (__half*)Cv;

    const int bm = blockIdx.y * 128, bn = blockIdx.x * 128;
    const int tid = threadIdx.x;
    const int wid = tid >> 5, lane = tid & 31;
    const int wm = (wid & 3) * 32, wn = (wid >> 2) * 64;
    const int q = lane >> 2, t = lane & 3;

    const uint32_t sbase = s2u(smh);
    const uint32_t STAGEB = 2 * 128 * GST * 4;
    // ldmatrix per-thread byte offsets (row stride 144B -> conflict-free)
    const uint32_t a_byte = (uint32_t)(wm + (lane & 15)) * (GST * 4) + ((lane >> 4) << 4);
    const uint32_t b_byte = (uint32_t)(wn + (lane & 7) + ((lane & 16) ? 8 : 0)) * (GST * 4)
                            + ((lane & 8) ? 16 : 0);

    float acc[2][8][4];
#pragma unroll
    for (int mi = 0; mi < 2; mi++)
#pragma unroll
        for (int ni = 0; ni < 8; ni++)
#pragma unroll
            for (int e = 0; e < 4; e++) acc[mi][ni][e] = 0.f;

    const int ktiles = K >> 6;

#define ISSUE(KT, STAGE)                                                      \
    {                                                                         \
        uint32_t* As = smh + (STAGE) * (2 * 128 * GST);                       \
        uint32_t* Bs = As + 128 * GST;                                        \
        int k0 = (KT) * 64;                                                   \
        _Pragma("unroll")                                                     \
        for (int rep = 0; rep < 4; rep++) {                                   \
            int idx = rep * 256 + tid;                                        \
            int row = idx >> 3, ch = idx & 7;                                 \
            cp16(As + row * GST + ch * 4,                                     \
                 A + (long long)(bm + row) * K + k0 + ch * 8, 16);            \
            int gb = bn + row;                                                \
            int gbc = gb < N ? gb : (N - 1);                                  \
            cp16(Bs + row * GST + ch * 4,                                     \
                 Bm + (long long)gbc * K + k0 + ch * 8, (gb < N) ? 16 : 0);   \
        }                                                                     \
        asm volatile("cp.async.commit_group;\n");                             \
    }

    ISSUE(0, 0);

    for (int kt = 0; kt < ktiles; kt++) {
        if (kt + 1 < ktiles) {
            ISSUE(kt + 1, (kt + 1) & 1);
            asm volatile("cp.async.wait_group 1;\n");
        } else {
            asm volatile("cp.async.wait_group 0;\n");
        }
        __syncthreads();

        const uint32_t As_s = sbase + (kt & 1) * STAGEB;
        const uint32_t Bs_s = As_s + 128 * GST * 4;
#pragma unroll
        for (int ks = 0; ks < 4; ks++) {
            const uint32_t kbB = ks * 32;
            uint32_t af[2][4];
            ldsm4(af[0], As_s + a_byte + kbB);
            ldsm4(af[1], As_s + a_byte + 16 * GST * 4 + kbB);
            uint32_t bf[8][2];
#pragma unroll
            for (int nj = 0; nj < 4; nj++) {
                uint32_t r[4];
                ldsm4(r, Bs_s + b_byte + nj * 16 * GST * 4 + kbB);
                bf[2 * nj][0] = r[0]; bf[2 * nj][1] = r[1];
                bf[2 * nj + 1][0] = r[2]; bf[2 * nj + 1][1] = r[3];
            }
#pragma unroll
            for (int mi = 0; mi < 2; mi++)
#pragma unroll
                for (int ni = 0; ni < 8; ni++)
                    mma_h(acc[mi][ni], af[mi], bf[ni]);
        }
        __syncthreads();
    }
#undef ISSUE

#pragma unroll
    for (int mi = 0; mi < 2; mi++)
#pragma unroll
        for (int ni = 0; ni < 8; ni++) {
            int gr0 = bm + wm + mi * 16 + q;
            int gc0 = bn + wn + ni * 8 + t * 2;
#pragma unroll
            for (int e = 0; e < 4; e++) {
                int gr = gr0 + ((e >= 2) ? 8 : 0);
                int gc = gc0 + (e & 1);
                if (gc >= N) continue;
                float v = acc[mi][ni][e];
                if (MODE == 0) {
                    Cf[(long long)gr * N + gc] = v;
                } else {
                    int b = gr >> 11, s = gr & 2047;
                    int h = gc >> 6, hd = gc & 63;
                    Ch[(((long long)b * H_ + h) * SQ_ + s) * HD_ + hd] = __float2half(v);
                }
            }
        }
}

// ---------------- banded flash attention (ldmatrix + double-buffered KV) ----
__global__ __launch_bounds__(256, 2) void attn_mma(
    const __half* __restrict__ qh, const __half* __restrict__ kh,
    const __half* __restrict__ vh, const float* __restrict__ qrel,
    __half* __restrict__ O)
{
    extern __shared__ uint32_t sma[];
    // layout: Qs[ATILE] | Ks[2][ATILE] | Vs[2][ATILE] | Ps[ATILE] | red[256]
    uint32_t* Qs  = sma;
    uint32_t* Ks0 = Qs + ATILE;
    uint32_t* Vs0 = Ks0 + 2 * ATILE;
    uint32_t* Ps  = Vs0 + 2 * ATILE;
    float* redm = (float*)(Ps + ATILE);   // [2][64]
    float* redl = redm + 128;             // [2][64]

    const int i0 = blockIdx.x * 64;
    const int h = blockIdx.y, b = blockIdx.z;
    const long long hb = (long long)(b * H_ + h);
    const uint32_t* qb = (const uint32_t*)(qh + hb * SQ_ * HD_);
    const uint32_t* kb = (const uint32_t*)(kh + hb * SK_ * HD_);
    const uint32_t* vb = (const uint32_t*)(vh + hb * SK_ * HD_);
    const float* qr = qrel + hb * SQ_ * P_;

    const int tid = threadIdx.x;
    const int wid = tid >> 5, lane = tid & 31;
    const int q = lane >> 2, t = lane & 3;
    const int wm = (wid & 3) * 16;
    const int wn = (wid >> 2) * 32;
    const int split = wid >> 2;
    const int r0 = wm + q, r1 = r0 + 8;

    const uint32_t sbase = s2u(sma);
    const uint32_t Qs_s = sbase;
    const uint32_t Ps_s = sbase + 5 * ATILE * 4;

    // ldmatrix byte offsets
    const uint32_t a_byte = (uint32_t)(wm + (lane & 15)) * (AST * 4) + ((lane >> 4) << 4);
    const uint32_t k_byte = (uint32_t)(wn + (lane & 7) + ((lane & 16) ? 8 : 0)) * (AST * 4)
                            + ((lane & 8) ? 16 : 0);
    // V (trans): row = key within 16-block, col = dim offset
    const uint32_t v_byte = (uint32_t)((lane & 7) + ((lane & 8) ? 8 : 0)) * (AST * 4)
                            + ((lane & 16) ? 16 : 0) + wn * 2;
    // stmatrix for P
    const uint32_t p_byte = (uint32_t)(wm + (lane & 15)) * (AST * 4)
                            + (wn / 2) * 4 + ((lane >> 4) << 4);

#define AISSUE(J0, S)                                                         \
    {                                                                         \
        uint32_t* Kd = Ks0 + (S) * ATILE;                                     \
        uint32_t* Vd = Vs0 + (S) * ATILE;                                     \
        _Pragma("unroll")                                                     \
        for (int l = tid; l < 512; l += 256) {                                \
            int r = l >> 3, ch = l & 7;                                       \
            cp16(Kd + r * AST + ch * 4,                                       \
                 kb + (long long)((J0) + r) * 32 + ch * 4, 16);               \
            cp16(Vd + r * AST + ch * 4,                                       \
                 vb + (long long)((J0) + r) * 32 + ch * 4, 16);               \
        }                                                                     \
        asm volatile("cp.async.commit_group;\n");                             \
    }

    int lo = i0 - RAD_;       if (lo < 0) lo = 0;
    int hi = i0 + 64 + RAD_;  if (hi > SK_) hi = SK_;

    // Q tile + first KV tile in one cp.async group
#pragma unroll
    for (int l = tid; l < 512; l += 256) {
        int r = l >> 3, ch = l & 7;
        cp16(Qs + r * AST + ch * 4, qb + (long long)(i0 + r) * 32 + ch * 4, 16);
    }
    AISSUE(lo, 0);

    float m_run[2] = {-1e30f, -1e30f};
    float l_run[2] = {0.f, 0.f};
    float oacc[4][4];
#pragma unroll
    for (int ni = 0; ni < 4; ni++)
#pragma unroll
        for (int e = 0; e < 4; e++) oacc[ni][e] = 0.f;

    int stage = 0;
    for (int j0 = lo; j0 < hi; j0 += 64) {
        if (j0 + 64 < hi) {
            AISSUE(j0 + 64, stage ^ 1);
            asm volatile("cp.async.wait_group 1;\n");
        } else {
            asm volatile("cp.async.wait_group 0;\n");
        }
        __syncthreads();

        const uint32_t Ks_s = sbase + (1 + stage) * ATILE * 4;
        const uint32_t Vs_s = sbase + (3 + stage) * ATILE * 4;

        // ---- S = Q K^T ----
        float sacc[4][4];
#pragma unroll
        for (int ni = 0; ni < 4; ni++)
#pragma unroll
            for (int e = 0; e < 4; e++) sacc[ni][e] = 0.f;
#pragma unroll
        for (int ks = 0; ks < 4; ks++) {
            const uint32_t kbB = ks * 32;
            uint32_t af[4];
            ldsm4(af, Qs_s + a_byte + kbB);
            uint32_t bf[4][2];
#pragma unroll
            for (int nj = 0; nj < 2; nj++) {
                uint32_t r[4];
                ldsm4(r, Ks_s + k_byte + nj * 16 * AST * 4 + kbB);
                bf[2 * nj][0] = r[0]; bf[2 * nj][1] = r[1];
                bf[2 * nj + 1][0] = r[2]; bf[2 * nj + 1][1] = r[3];
            }
#pragma unroll
            for (int ni = 0; ni < 4; ni++)
                mma_h(sacc[ni], af, bf[ni]);
        }

        // ---- rel gather + mask + scale; row max ----
        float mloc[2] = {-1e30f, -1e30f};
#pragma unroll
        for (int ni = 0; ni < 4; ni++)
#pragma unroll
            for (int e = 0; e < 4; e++) {
                int ri = e >> 1;
                int rl = ri ? r1 : r0;
                int c = wn + ni * 8 + t * 2 + (e & 1);
                int delta = (j0 + c) - (i0 + rl);
                float s = -1e30f;
                if (delta >= -RAD_ && delta <= RAD_) {
                    int pid = min(max(delta, -R_), R_) + R_;
                    s = (sacc[ni][e] +
                         __ldg(qr + (long long)(i0 + rl) * P_ + pid)) * 0.125f;
                }
                sacc[ni][e] = s;
                mloc[ri] = fmaxf(mloc[ri], s);
            }
#pragma unroll
        for (int i = 0; i < 2; i++) {
            mloc[i] = fmaxf(mloc[i], __shfl_xor_sync(0xffffffffu, mloc[i], 1));
            mloc[i] = fmaxf(mloc[i], __shfl_xor_sync(0xffffffffu, mloc[i], 2));
        }
        if (t == 0) {
            redm[split * 64 + r0] = mloc[0];
            redm[split * 64 + r1] = mloc[1];
        }
        __syncthreads();

        float mnew[2], f[2];
#pragma unroll
        for (int i = 0; i < 2; i++) {
            int rl = i ? r1 : r0;
            float mt = fmaxf(redm[rl], redm[64 + rl]);
            mnew[i] = fmaxf(m_run[i], mt);
            f[i] = __expf(m_run[i] - mnew[i]);
            m_run[i] = mnew[i];
        }

        // ---- exp, pack P, stmatrix to smem, partial sums ----
        float sloc[2] = {0.f, 0.f};
        uint32_t pk[4][2];
#pragma unroll
        for (int ni = 0; ni < 4; ni++)
#pragma unroll
            for (int ri = 0; ri < 2; ri++) {
                float p0 = __expf(sacc[ni][ri * 2 + 0] - mnew[ri]);
                float p1 = __expf(sacc[ni][ri * 2 + 1] - mnew[ri]);
                sloc[ri] += p0 + p1;
                pk[ni][ri] = packh2(p0, p1);
            }
#pragma unroll
        for (int nj = 0; nj < 2; nj++)
            stsm4(Ps_s + p_byte + nj * 32,
                  pk[2 * nj][0], pk[2 * nj][1], pk[2 * nj + 1][0], pk[2 * nj + 1][1]);
#pragma unroll
        for (int i = 0; i < 2; i++) {
            sloc[i] += __shfl_xor_sync(0xffffffffu, sloc[i], 1);
            sloc[i] += __shfl_xor_sync(0xffffffffu, sloc[i], 2);
        }
        if (t == 0) {
            redl[split * 64 + r0] = sloc[0];
            redl[split * 64 + r1] = sloc[1];
        }
        __syncthreads();

#pragma unroll
        for (int i = 0; i < 2; i++) {
            int rl = i ? r1 : r0;
            l_run[i] = l_run[i] * f[i] + redl[rl] + redl[64 + rl];
        }
#pragma unroll
        for (int ni = 0; ni < 4; ni++)
#pragma unroll
            for (int e = 0; e < 4; e++) oacc[ni][e] *= f[e >> 1];

        // ---- O += P V  (V row-major, trans ldmatrix for B frags) ----
#pragma unroll
        for (int ks = 0; ks < 4; ks++) {
            const uint32_t kbB = ks * 32;
            uint32_t af[4];
            ldsm4(af, Ps_s + a_byte + kbB);
            uint32_t bf[4][2];
#pragma unroll
            for (int nj = 0; nj < 2; nj++) {
                uint32_t r[4];
                ldsm4t(r, Vs_s + v_byte + ks * 16 * AST * 4 + nj * 32);
                bf[2 * nj][0] = r[0]; bf[2 * nj][1] = r[1];
                bf[2 * nj + 1][0] = r[2]; bf[2 * nj + 1][1] = r[3];
            }
#pragma unroll
            for (int ni = 0; ni < 4; ni++)
                mma_h(oacc[ni], af, bf[ni]);
        }
        __syncthreads();
        stage ^= 1;
    }
#undef AISSUE

    // ---- normalize + store O[b][s][hd*H + h] as fp16 ----
    float inv[2] = {1.f / l_run[0], 1.f / l_run[1]};
#pragma unroll
    for (int ni = 0; ni < 4; ni++)
#pragma unroll
        for (int e = 0; e < 4; e++) {
            int ri = e >> 1;
            int rl = ri ? r1 : r0;
            int c = wn + ni * 8 + t * 2 + (e & 1);
            O[((long long)b * SQ_ + i0 + rl) * D_ + c * H_ + h] =
                __float2half(oacc[ni][e] * inv[ri]);
        }
}

// ---------------- launch -----------------------------------------------------
extern "C" void kernel_launch(void* const* d_in, const int* in_sizes, int n_in,
                              void* d_out, int out_size)
{
    const float* Q  = (const float*)d_in[0];
    const float* K  = (const float*)d_in[1];
    const float* V  = (const float*)d_in[2];
    const float* Wq = (const float*)d_in[3];
    const float* Wk = (const float*)d_in[4];
    const float* Wv = (const float*)d_in[5];
    const float* Wo = (const float*)d_in[6];
    const float* E  = (const float*)d_in[7];
    float* out = (float*)d_out;

    __half *xf, *wh, *qh, *kh, *vh, *relT, *o;
    float *qrel;
    cudaGetSymbolAddress((void**)&xf,   g_xf);
    cudaGetSymbolAddress((void**)&wh,   g_wh);
    cudaGetSymbolAddress((void**)&qh,   g_qh);
    cudaGetSymbolAddress((void**)&kh,   g_kh);
    cudaGetSymbolAddress((void**)&vh,   g_vh);
    cudaGetSymbolAddress((void**)&relT, g_relT);
    cudaGetSymbolAddress((void**)&qrel, g_qrel);
    cudaGetSymbolAddress((void**)&o,    g_o);

    __half* qf = xf + 0 * (size_t)B_ * SQ_ * D_;
    __half* kf = xf + 1 * (size_t)B_ * SQ_ * D_;
    __half* vf = xf + 2 * (size_t)B_ * SQ_ * D_;

    const int gemm_smem = 2 * 2 * 128 * GST * (int)sizeof(uint32_t);   // 73728
    cudaFuncSetAttribute((const void*)gemm_h<0>, cudaFuncAttributeMaxDynamicSharedMemorySize, gemm_smem);
    cudaFuncSetAttribute((const void*)gemm_h<1>, cudaFuncAttributeMaxDynamicSharedMemorySize, gemm_smem);

    dim3 blk(256);
    dim3 gproj(1024 / 128, 4096 / 128, 1);

    // prologue conversions
    int nx4 = B_ * SQ_ * D_ / 4;
    cvt_qkv<<<(nx4 + 255) / 256, 256>>>(Q, K, V, qf, kf, vf, nx4);
    int nW4 = D_ * D_ / 4;
    cvt_w<<<(nW4 + 255) / 256, 256>>>(Wq, Wk, Wv, Wo, wh, nW4);
    int nE = H_ * P_ * HD_;
    transpose_E<<<(nE + 255) / 256, 256>>>(E, relT);

    // projections -> head-split fp16
    gemm_h<1><<<gproj, blk, gemm_smem>>>(qf, wh + 0 * (size_t)D_ * D_, qh, 4096, 1024, 1024, 0, 0, 0, 1);
    gemm_h<1><<<gproj, blk, gemm_smem>>>(kf, wh + 1 * (size_t)D_ * D_, kh, 4096, 1024, 1024, 0, 0, 0, 1);
    gemm_h<1><<<gproj, blk, gemm_smem>>>(vf, wh + 2 * (size_t)D_ * D_, vh, 4096, 1024, 1024, 0, 0, 0, 1);

    // Q_rel (K=64, one k-tile)
    dim3 gqr((P_ + 127) / 128, SQ_ / 128, B_ * H_);
    gemm_h<0><<<gqr, blk, gemm_smem>>>(qh, relT, qrel, SQ_, P_, HD_,
                                       (long long)SQ_ * HD_, (long long)P_ * HD_,
                                       (long long)SQ_ * P_, H_);

    // banded attention (double-buffered KV)
    int asmem = 6 * ATILE * (int)sizeof(uint32_t) + 256 * (int)sizeof(float);  // 56320
    cudaFuncSetAttribute(attn_mma, cudaFuncAttributeMaxDynamicSharedMemorySize, asmem);
    dim3 gattn(SQ_ / 64, H_, B_);
    attn_mma<<<gattn, blk, asmem>>>(qh, kh, vh, qrel, o);

    // output projection -> fp32 out
    gemm_h<0><<<gproj, blk, gemm_smem>>>(o, wh + 3 * (size_t)D_ * D_, out, 4096, 1024, 1024, 0, 0, 0, 1);

    (void)in_sizes; (void)n_in; (void)out_size;
}

// round 8
// speedup vs baseline: 4.9252x; 1.0604x over previous
#include <cuda_runtime.h>
#include <cuda_fp16.h>
#include <cstdint>

#define B_   2
#define SQ_  2048
#define SK_  2048
#define D_   1024
#define H_   16
#define HD_  64
#define P_   257
#define R_   128
#define RAD_ 256

#define GST 36             // gemm smem row stride in uint32 units
#define AST 36             // attention smem row stride in uint32 units
#define ATILE (64 * AST)   // uint32s per 64-row attention KV tile
#define QROWS 128
#define HS ((size_t)B_ * H_ * SQ_ * HD_)

// ---------------- scratch (device globals; no allocation allowed) -----------
__device__ __half g_xf[3][(size_t)B_ * SQ_ * D_];
__device__ __half g_wh[4][(size_t)D_ * D_];
__device__ __half g_heads[3 * HS];                 // qh | kh | vh
__device__ __half g_relT[(size_t)H_ * P_ * HD_];
__device__ float  g_qrel[(size_t)B_ * H_ * SQ_ * P_];
__device__ __half g_o[(size_t)B_ * SQ_ * D_];

// ---------------- helpers ----------------------------------------------------
__device__ __forceinline__ void mma_h(float* c, const uint32_t* a, const uint32_t* b) {
    asm volatile(
        "mma.sync.aligned.m16n8k16.row.col.f32.f16.f16.f32 "
        "{%0,%1,%2,%3}, {%4,%5,%6,%7}, {%8,%9}, {%0,%1,%2,%3};"
        : "+f"(c[0]), "+f"(c[1]), "+f"(c[2]), "+f"(c[3])
        : "r"(a[0]), "r"(a[1]), "r"(a[2]), "r"(a[3]), "r"(b[0]), "r"(b[1]));
}

__device__ __forceinline__ void ldsm4(uint32_t* r, uint32_t saddr) {
    asm volatile("ldmatrix.sync.aligned.m8n8.x4.shared.b16 {%0,%1,%2,%3}, [%4];"
                 : "=r"(r[0]), "=r"(r[1]), "=r"(r[2]), "=r"(r[3]) : "r"(saddr));
}

__device__ __forceinline__ void ldsm4t(uint32_t* r, uint32_t saddr) {
    asm volatile("ldmatrix.sync.aligned.m8n8.x4.trans.shared.b16 {%0,%1,%2,%3}, [%4];"
                 : "=r"(r[0]), "=r"(r[1]), "=r"(r[2]), "=r"(r[3]) : "r"(saddr));
}

__device__ __forceinline__ void cp16(void* dst_s, const void* src_g, int sz) {
    uint32_t dst = (uint32_t)__cvta_generic_to_shared(dst_s);
    asm volatile("cp.async.cg.shared.global [%0], [%1], 16, %2;\n"
                 :: "r"(dst), "l"(src_g), "r"(sz));
}

__device__ __forceinline__ uint32_t s2u(const void* p) {
    return (uint32_t)__cvta_generic_to_shared(p);
}

__device__ __forceinline__ uint32_t packh2(float x, float y) {
    __half2 h = __floats2half2_rn(x, y);
    return *(uint32_t*)&h;
}

// ---------------- prologue conversions ---------------------------------------
__global__ void cvt_qkv(const float* __restrict__ Q, const float* __restrict__ K,
                        const float* __restrict__ V, __half* __restrict__ qf,
                        __half* __restrict__ kf, __half* __restrict__ vf, int n4)
{
    int i = blockIdx.x * blockDim.x + threadIdx.x;
    if (i >= n4) return;
    float4 a = ((const float4*)Q)[i];
    ((uint2*)qf)[i] = make_uint2(packh2(a.x, a.y), packh2(a.z, a.w));
    float4 b = ((const float4*)K)[i];
    ((uint2*)kf)[i] = make_uint2(packh2(b.x, b.y), packh2(b.z, b.w));
    float4 c = ((const float4*)V)[i];
    ((uint2*)vf)[i] = make_uint2(packh2(c.x, c.y), packh2(c.z, c.w));
}

__global__ void cvt_w(const float* __restrict__ w0, const float* __restrict__ w1,
                      const float* __restrict__ w2, const float* __restrict__ w3,
                      __half* __restrict__ dst, int n4)
{
    int i = blockIdx.x * blockDim.x + threadIdx.x;
    if (i >= n4) return;
    const float* srcs[4] = {w0, w1, w2, w3};
#pragma unroll
    for (int m = 0; m < 4; m++) {
        float4 a = ((const float4*)srcs[m])[i];
        ((uint2*)(dst + (size_t)m * D_ * D_))[i] =
            make_uint2(packh2(a.x, a.y), packh2(a.z, a.w));
    }
}

__global__ void transpose_E(const float* __restrict__ E, __half* __restrict__ relT)
{
    int idx = blockIdx.x * blockDim.x + threadIdx.x;
    if (idx >= H_ * P_ * HD_) return;
    int h = idx / (P_ * HD_);
    int rem = idx % (P_ * HD_);
    int p = rem / HD_;
    int d = rem % HD_;
    relT[idx] = __float2half(E[(long long)p * D_ + d * H_ + h]);
}

// ---------------- fp16 tensor-core NT GEMM (3-stage, 1 barrier/ktile) -------
template <int MODE>
__global__ __launch_bounds__(256, 2) void gemm_h(
    const __half* __restrict__ A, const __half* __restrict__ Bm,
    void* __restrict__ Cv, int M, int N, int K,
    long long sA, long long sB, long long sC, int bmodB)
{
    extern __shared__ uint32_t smh[];   // 3 stages * 2 * 128 * GST
    const int z = blockIdx.z;
    A  += (long long)z * sA;
    Bm += (long long)(z % bmodB) * sB;
    float* Cf = (float*)Cv + (long long)z * sC;
    __half* Ch = (__half*)Cv + (long long)z * sC;

    const int bm = blockIdx.y * 128, bn = blockIdx.x * 128;
    const int tid = threadIdx.x;
    const int wid = tid >> 5, lane = tid & 31;
    const int wm = (wid & 3) * 32, wn = (wid >> 2) * 64;
    const int q = lane >> 2, t = lane & 3;

    const uint32_t sbase = s2u(smh);
    const uint32_t STAGEB = 2 * 128 * GST * 4;
    const uint32_t a_byte = (uint32_t)(wm + (lane & 15)) * (GST * 4) + ((lane >> 4) << 4);
    const uint32_t b_byte = (uint32_t)(wn + (lane & 7) + ((lane & 16) ? 8 : 0)) * (GST * 4)
                            + ((lane & 8) ? 16 : 0);

    float acc[2][8][4];
#pragma unroll
    for (int mi = 0; mi < 2; mi++)
#pragma unroll
        for (int ni = 0; ni < 8; ni++)
#pragma unroll
            for (int e = 0; e < 4; e++) acc[mi][ni][e] = 0.f;

    const int ktiles = K >> 6;

#define ISSUE(KT, STAGE)                                                      \
    {                                                                         \
        uint32_t* As = smh + (STAGE) * (2 * 128 * GST);                       \
        uint32_t* Bs = As + 128 * GST;                                        \
        int k0 = (KT) * 64;                                                   \
        _Pragma("unroll")                                                     \
        for (int rep = 0; rep < 4; rep++) {                                   \
            int idx = rep * 256 + tid;                                        \
            int row = idx >> 3, ch = idx & 7;                                 \
            cp16(As + row * GST + ch * 4,                                     \
                 A + (long long)(bm + row) * K + k0 + ch * 8, 16);            \
            int gb = bn + row;                                                \
            int gbc = gb < N ? gb : (N - 1);                                  \
            cp16(Bs + row * GST + ch * 4,                                     \
                 Bm + (long long)gbc * K + k0 + ch * 8, (gb < N) ? 16 : 0);   \
        }                                                                     \
        asm volatile("cp.async.commit_group;\n");                             \
    }

    ISSUE(0, 0);
    if (ktiles > 1) ISSUE(1, 1);

    for (int kt = 0; kt < ktiles; kt++) {
        if (kt + 1 < ktiles) {
            asm volatile("cp.async.wait_group 1;\n");
        } else {
            asm volatile("cp.async.wait_group 0;\n");
        }
        __syncthreads();
        if (kt + 2 < ktiles) ISSUE(kt + 2, (kt + 2) % 3);

        const uint32_t As_s = sbase + (kt % 3) * STAGEB;
        const uint32_t Bs_s = As_s + 128 * GST * 4;
#pragma unroll
        for (int ks = 0; ks < 4; ks++) {
            const uint32_t kbB = ks * 32;
            uint32_t af[2][4];
            ldsm4(af[0], As_s + a_byte + kbB);
            ldsm4(af[1], As_s + a_byte + 16 * GST * 4 + kbB);
            uint32_t bf[8][2];
#pragma unroll
            for (int nj = 0; nj < 4; nj++) {
                uint32_t r[4];
                ldsm4(r, Bs_s + b_byte + nj * 16 * GST * 4 + kbB);
                bf[2 * nj][0] = r[0]; bf[2 * nj][1] = r[1];
                bf[2 * nj + 1][0] = r[2]; bf[2 * nj + 1][1] = r[3];
            }
#pragma unroll
            for (int mi = 0; mi < 2; mi++)
#pragma unroll
                for (int ni = 0; ni < 8; ni++)
                    mma_h(acc[mi][ni], af[mi], bf[ni]);
        }
    }
#undef ISSUE

#pragma unroll
    for (int mi = 0; mi < 2; mi++)
#pragma unroll
        for (int ni = 0; ni < 8; ni++) {
            int gr0 = bm + wm + mi * 16 + q;
            int gc0 = bn + wn + ni * 8 + t * 2;
#pragma unroll
            for (int e = 0; e < 4; e++) {
                int gr = gr0 + ((e >= 2) ? 8 : 0);
                int gc = gc0 + (e & 1);
                if (gc >= N) continue;
                float v = acc[mi][ni][e];
                if (MODE == 0) {
                    Cf[(long long)gr * N + gc] = v;
                } else {
                    int b = gr >> 11, s = gr & 2047;
                    int h = gc >> 6, hd = gc & 63;
                    Ch[(((long long)b * H_ + h) * SQ_ + s) * HD_ + hd] = __float2half(v);
                }
            }
        }
}

// ---------------- banded flash attention: 128-row tiles, warp-local rows ----
__global__ __launch_bounds__(256, 2) void attn_mma(
    const __half* __restrict__ qh, const __half* __restrict__ kh,
    const __half* __restrict__ vh, const float* __restrict__ qrel,
    __half* __restrict__ O)
{
    extern __shared__ uint32_t sma[];
    uint32_t* Qs  = sma;                       // [QROWS][AST]
    uint32_t* Ks0 = Qs + QROWS * AST;          // [2][ATILE]
    uint32_t* Vs0 = Ks0 + 2 * ATILE;           // [2][ATILE]

    const int i0 = blockIdx.x * QROWS;
    const int h = blockIdx.y, b = blockIdx.z;
    const long long hb = (long long)(b * H_ + h);
    const uint32_t* qb = (const uint32_t*)(qh + hb * SQ_ * HD_);
    const uint32_t* kb = (const uint32_t*)(kh + hb * SK_ * HD_);
    const uint32_t* vb = (const uint32_t*)(vh + hb * SK_ * HD_);
    const float* qr = qrel + hb * SQ_ * P_;

    const int tid = threadIdx.x;
    const int wid = tid >> 5, lane = tid & 31;
    const int q = lane >> 2, t = lane & 3;
    const int wm = wid * 16;                   // warp owns rows [wm, wm+16)
    const int r0 = wm + q, r1 = r0 + 8;

    const uint32_t sbase = s2u(sma);
    const uint32_t Qs_s = sbase;
    const uint32_t Kbase = sbase + QROWS * AST * 4;
    const uint32_t Vbase = Kbase + 2 * ATILE * 4;

    const uint32_t a_byte = (uint32_t)(wm + (lane & 15)) * (AST * 4) + ((lane >> 4) << 4);
    const uint32_t k_byte = (uint32_t)((lane & 7) + ((lane & 16) ? 8 : 0)) * (AST * 4)
                            + ((lane & 8) ? 16 : 0);
    const uint32_t v_byte = (uint32_t)((lane & 7) + ((lane & 8) ? 8 : 0)) * (AST * 4)
                            + ((lane & 16) ? 16 : 0);

#define AISSUE(J0, S)                                                         \
    {                                                                         \
        uint32_t* Kd = Ks0 + (S) * ATILE;                                     \
        uint32_t* Vd = Vs0 + (S) * ATILE;                                     \
        _Pragma("unroll")                                                     \
        for (int l = tid; l < 512; l += 256) {                                \
            int r = l >> 3, ch = l & 7;                                       \
            cp16(Kd + r * AST + ch * 4,                                       \
                 kb + (long long)((J0) + r) * 32 + ch * 4, 16);               \
            cp16(Vd + r * AST + ch * 4,                                       \
                 vb + (long long)((J0) + r) * 32 + ch * 4, 16);               \
        }                                                                     \
        asm volatile("cp.async.commit_group;\n");                             \
    }

    int lo = i0 - RAD_;           if (lo < 0) lo = 0;
    int hi = i0 + QROWS + RAD_;   if (hi > SK_) hi = SK_;

    // Q tile + first KV tile (one cp.async group)
#pragma unroll
    for (int l = tid; l < 1024; l += 256) {
        int r = l >> 3, ch = l & 7;
        cp16(Qs + r * AST + ch * 4, qb + (long long)(i0 + r) * 32 + ch * 4, 16);
    }
    AISSUE(lo, 0);

    float m_run[2] = {-1e30f, -1e30f};
    float l_run[2] = {0.f, 0.f};
    float oacc[8][4];
#pragma unroll
    for (int ni = 0; ni < 8; ni++)
#pragma unroll
        for (int e = 0; e < 4; e++) oacc[ni][e] = 0.f;

    int stage = 0;
    for (int j0 = lo; j0 < hi; j0 += 64) {
        asm volatile("cp.async.wait_group 0;\n");
        __syncthreads();
        if (j0 + 64 < hi) AISSUE(j0 + 64, stage ^ 1);

        const uint32_t Ks_s = Kbase + stage * ATILE * 4;
        const uint32_t Vs_s = Vbase + stage * ATILE * 4;

        // ---- S = Q K^T : 16 rows x 64 keys per warp ----
        float sacc[8][4];
#pragma unroll
        for (int ni = 0; ni < 8; ni++)
#pragma unroll
            for (int e = 0; e < 4; e++) sacc[ni][e] = 0.f;
#pragma unroll
        for (int ks = 0; ks < 4; ks++) {
            const uint32_t kbB = ks * 32;
            uint32_t af[4];
            ldsm4(af, Qs_s + a_byte + kbB);
#pragma unroll
            for (int nj = 0; nj < 4; nj++) {
                uint32_t r[4];
                ldsm4(r, Ks_s + k_byte + nj * 16 * AST * 4 + kbB);
                uint32_t bf0[2] = {r[0], r[1]};
                uint32_t bf1[2] = {r[2], r[3]};
                mma_h(sacc[2 * nj], af, bf0);
                mma_h(sacc[2 * nj + 1], af, bf1);
            }
        }

        // ---- rel gather + mask + scale; warp-local row max ----
        float mloc[2] = {-1e30f, -1e30f};
#pragma unroll
        for (int ni = 0; ni < 8; ni++)
#pragma unroll
            for (int e = 0; e < 4; e++) {
                int ri = e >> 1;
                int rl = ri ? r1 : r0;
                int c = ni * 8 + t * 2 + (e & 1);
                int delta = (j0 + c) - (i0 + rl);
                float s = -1e30f;
                if (delta >= -RAD_ && delta <= RAD_) {
                    int pid = min(max(delta, -R_), R_) + R_;
                    s = (sacc[ni][e] +
                         __ldg(qr + (long long)(i0 + rl) * P_ + pid)) * 0.125f;
                }
                sacc[ni][e] = s;
                mloc[ri] = fmaxf(mloc[ri], s);
            }
        float mnew[2], f[2];
#pragma unroll
        for (int i = 0; i < 2; i++) {
            mloc[i] = fmaxf(mloc[i], __shfl_xor_sync(0xffffffffu, mloc[i], 1));
            mloc[i] = fmaxf(mloc[i], __shfl_xor_sync(0xffffffffu, mloc[i], 2));
            // clamp: a fully-masked leading tile must give p = 0, not exp(0)
            mnew[i] = fmaxf(fmaxf(m_run[i], mloc[i]), -1e29f);
            f[i] = __expf(m_run[i] - mnew[i]);
            m_run[i] = mnew[i];
        }

        // ---- exp in-place; warp-local row sums ----
        float sloc[2] = {0.f, 0.f};
#pragma unroll
        for (int ni = 0; ni < 8; ni++)
#pragma unroll
            for (int e = 0; e < 4; e++) {
                int ri = e >> 1;
                float p = __expf(sacc[ni][e] - mnew[ri]);
                sacc[ni][e] = p;
                sloc[ri] += p;
            }
#pragma unroll
        for (int i = 0; i < 2; i++) {
            sloc[i] += __shfl_xor_sync(0xffffffffu, sloc[i], 1);
            sloc[i] += __shfl_xor_sync(0xffffffffu, sloc[i], 2);
            l_run[i] = l_run[i] * f[i] + sloc[i];
        }
#pragma unroll
        for (int ni = 0; ni < 8; ni++)
#pragma unroll
            for (int e = 0; e < 4; e++) oacc[ni][e] *= f[e >> 1];

        // ---- O += P V : QK C-frags pass directly into PV A-frags ----
#pragma unroll
        for (int ks = 0; ks < 4; ks++) {
            uint32_t af[4];
            af[0] = packh2(sacc[2 * ks][0], sacc[2 * ks][1]);
            af[1] = packh2(sacc[2 * ks][2], sacc[2 * ks][3]);
            af[2] = packh2(sacc[2 * ks + 1][0], sacc[2 * ks + 1][1]);
            af[3] = packh2(sacc[2 * ks + 1][2], sacc[2 * ks + 1][3]);
#pragma unroll
            for (int nj = 0; nj < 4; nj++) {
                uint32_t r[4];
                ldsm4t(r, Vs_s + v_byte + ks * 16 * AST * 4 + nj * 32);
                uint32_t bf0[2] = {r[0], r[1]};
                uint32_t bf1[2] = {r[2], r[3]};
                mma_h(oacc[2 * nj], af, bf0);
                mma_h(oacc[2 * nj + 1], af, bf1);
            }
        }
        stage ^= 1;
    }
#undef AISSUE

    // ---- normalize + store O[b][s][hd*H + h] as fp16 ----
    float inv[2] = {1.f / l_run[0], 1.f / l_run[1]};
#pragma unroll
    for (int ni = 0; ni < 8; ni++)
#pragma unroll
        for (int e = 0; e < 4; e++) {
            int ri = e >> 1;
            int rl = ri ? r1 : r0;
            int c = ni * 8 + t * 2 + (e & 1);
            O[((long long)b * SQ_ + i0 + rl) * D_ + c * H_ + h] =
                __float2half(oacc[ni][e] * inv[ri]);
        }
}

// ---------------- launch -----------------------------------------------------
extern "C" void kernel_launch(void* const* d_in, const int* in_sizes, int n_in,
                              void* d_out, int out_size)
{
    const float* Q  = (const float*)d_in[0];
    const float* K  = (const float*)d_in[1];
    const float* V  = (const float*)d_in[2];
    const float* Wq = (const float*)d_in[3];
    const float* Wk = (const float*)d_in[4];
    const float* Wv = (const float*)d_in[5];
    const float* Wo = (const float*)d_in[6];
    const float* E  = (const float*)d_in[7];
    float* out = (float*)d_out;

    __half *xf, *wh, *heads, *relT, *o;
    float *qrel;
    cudaGetSymbolAddress((void**)&xf,    g_xf);
    cudaGetSymbolAddress((void**)&wh,    g_wh);
    cudaGetSymbolAddress((void**)&heads, g_heads);
    cudaGetSymbolAddress((void**)&relT,  g_relT);
    cudaGetSymbolAddress((void**)&qrel,  g_qrel);
    cudaGetSymbolAddress((void**)&o,     g_o);

    __half* qf = xf + 0 * (size_t)B_ * SQ_ * D_;
    __half* kf = xf + 1 * (size_t)B_ * SQ_ * D_;
    __half* vf = xf + 2 * (size_t)B_ * SQ_ * D_;
    __half* qh = heads;
    __half* kh = heads + HS;
    __half* vh = heads + 2 * HS;

    const int gemm_smem = 3 * 2 * 128 * GST * (int)sizeof(uint32_t);   // 110592
    cudaFuncSetAttribute((const void*)gemm_h<0>, cudaFuncAttributeMaxDynamicSharedMemorySize, gemm_smem);
    cudaFuncSetAttribute((const void*)gemm_h<1>, cudaFuncAttributeMaxDynamicSharedMemorySize, gemm_smem);

    dim3 blk(256);

    // prologue conversions
    int nx4 = B_ * SQ_ * D_ / 4;
    cvt_qkv<<<(nx4 + 255) / 256, 256>>>(Q, K, V, qf, kf, vf, nx4);
    int nW4 = D_ * D_ / 4;
    cvt_w<<<(nW4 + 255) / 256, 256>>>(Wq, Wk, Wv, Wo, wh, nW4);
    int nE = H_ * P_ * HD_;
    transpose_E<<<(nE + 255) / 256, 256>>>(E, relT);

    // fused Q/K/V projections: z = 0..2 selects (input, weight, output)
    dim3 gproj(1024 / 128, 4096 / 128, 3);
    gemm_h<1><<<gproj, blk, gemm_smem>>>(qf, wh, heads, 4096, 1024, 1024,
                                         (long long)B_ * SQ_ * D_, (long long)D_ * D_,
                                         (long long)HS, 3);

    // Q_rel: per (b,h)
    dim3 gqr((P_ + 127) / 128, SQ_ / 128, B_ * H_);
    gemm_h<0><<<gqr, blk, gemm_smem>>>(qh, relT, qrel, SQ_, P_, HD_,
                                       (long long)SQ_ * HD_, (long long)P_ * HD_,
                                       (long long)SQ_ * P_, H_);

    // banded attention: 128-row tiles
    int asmem = (QROWS * AST + 4 * ATILE) * (int)sizeof(uint32_t);   // 55296
    cudaFuncSetAttribute(attn_mma, cudaFuncAttributeMaxDynamicSharedMemorySize, asmem);
    dim3 gattn(SQ_ / QROWS, H_, B_);
    attn_mma<<<gattn, blk, asmem>>>(qh, kh, vh, qrel, o);

    // output projection -> fp32 out
    dim3 gout(1024 / 128, 4096 / 128, 1);
    gemm_h<0><<<gout, blk, gemm_smem>>>(o, wh + 3 * (size_t)D_ * D_, out, 4096, 1024, 1024,
                                        0, 0, 0, 1);

    (void)in_sizes; (void)n_in; (void)out_size;
}